// round 6
// baseline (speedup 1.0000x reference)
#include <cuda_runtime.h>
#include <cuda_bf16.h>
#include <cstdint>
#include <math.h>

#define B_   8
#define N_   1024
#define DM_  512
#define H_   8
#define MT_  (B_ * N_)      // 8192

// ---------------- bf16 scratch (__device__ globals; no allocs) -------------
__device__ __nv_bfloat16 g_curhi[MT_ * DM_], g_curlo[MT_ * DM_];
__device__ __nv_bfloat16 g_hidhi[MT_ * DM_], g_hidlo[MT_ * DM_];
__device__ __nv_bfloat16 g_wqThi [DM_ * DM_],     g_wqTlo [DM_ * DM_];
__device__ __nv_bfloat16 g_wkvThi[2 * DM_ * DM_], g_wkvTlo[2 * DM_ * DM_];
__device__ __nv_bfloat16 g_woThi [DM_ * DM_],     g_woTlo [DM_ * DM_];
__device__ __nv_bfloat16 g_qhi [MT_ * DM_],     g_qlo [MT_ * DM_];
__device__ __nv_bfloat16 g_kvhi[MT_ * 2 * DM_], g_kvlo[MT_ * 2 * DM_];
__device__ __nv_bfloat16 g_aohi[MT_ * DM_],     g_aolo[MT_ * DM_];

// ---------------- helpers ---------------------------------------------------
__device__ __forceinline__ uint32_t smem_u32(const void* p) {
    uint32_t a;
    asm("{ .reg .u64 t; cvta.to.shared.u64 t, %1; cvt.u32.u64 %0, t; }" : "=r"(a) : "l"(p));
    return a;
}
__device__ __forceinline__ void cpa16(uint32_t dst, const void* src) {
    asm volatile("cp.async.cg.shared.global [%0], [%1], 16;" :: "r"(dst), "l"(src));
}
#define CP_COMMIT() asm volatile("cp.async.commit_group;" ::: "memory")
#define CP_WAIT(n)  asm volatile("cp.async.wait_group %0;" :: "n"(n) : "memory")

__device__ __forceinline__ void ldsm4(uint32_t* r, uint32_t addr) {
    asm volatile("ldmatrix.sync.aligned.m8n8.x4.shared.b16 {%0,%1,%2,%3}, [%4];"
        : "=r"(r[0]), "=r"(r[1]), "=r"(r[2]), "=r"(r[3]) : "r"(addr));
}
__device__ __forceinline__ void ldsm4t(uint32_t* r, uint32_t addr) {
    asm volatile("ldmatrix.sync.aligned.m8n8.x4.trans.shared.b16 {%0,%1,%2,%3}, [%4];"
        : "=r"(r[0]), "=r"(r[1]), "=r"(r[2]), "=r"(r[3]) : "r"(addr));
}
__device__ __forceinline__ void mma16816(float* c, const uint32_t* a, const uint32_t* b) {
    asm volatile("mma.sync.aligned.m16n8k16.row.col.f32.bf16.bf16.f32 "
        "{%0,%1,%2,%3}, {%4,%5,%6,%7}, {%8,%9}, {%0,%1,%2,%3};"
        : "+f"(c[0]), "+f"(c[1]), "+f"(c[2]), "+f"(c[3])
        : "r"(a[0]), "r"(a[1]), "r"(a[2]), "r"(a[3]), "r"(b[0]), "r"(b[1]));
}
__device__ __forceinline__ uint32_t bpack(__nv_bfloat16 a, __nv_bfloat16 b) {
    __nv_bfloat162 t; t.x = a; t.y = b;
    return *(uint32_t*)&t;
}
__device__ __forceinline__ void split2(float v0, float v1, uint32_t& hi, uint32_t& lo) {
    __nv_bfloat16 h0 = __float2bfloat16(v0), h1 = __float2bfloat16(v1);
    __nv_bfloat16 l0 = __float2bfloat16(v0 - __bfloat162float(h0));
    __nv_bfloat16 l1 = __float2bfloat16(v1 - __bfloat162float(h1));
    hi = bpack(h0, h1); lo = bpack(l0, l1);
}

// smem rows are 144 bytes (72 bf16) -> conflict-free ldmatrix
__device__ __forceinline__ uint32_t addrA(uint32_t base, int row, int col, int l) {
    return base + (uint32_t)((row + (l & 15)) * 144 + (col + (l >> 4) * 8) * 2);
}
__device__ __forceinline__ uint32_t addrB(uint32_t base, int row, int col, int l) {
    return base + (uint32_t)((row + ((l >> 4) & 1) * 8 + (l & 7)) * 144
                             + (col + ((l >> 3) & 1) * 8) * 2);
}

// ---------------------------------------------------------------------------
// conversion kernels
// ---------------------------------------------------------------------------
__global__ void split_two(const float* __restrict__ x0, const float* __restrict__ x1,
                          __nv_bfloat16* __restrict__ h0, __nv_bfloat16* __restrict__ l0p,
                          __nv_bfloat16* __restrict__ h1, __nv_bfloat16* __restrict__ l1p,
                          int n4)
{
    int i = blockIdx.x * blockDim.x + threadIdx.x;
    const float* x = (i < n4) ? x0 : x1;
    __nv_bfloat16* hh = (i < n4) ? h0 : h1;
    __nv_bfloat16* ll = (i < n4) ? l0p : l1p;
    int j = (i < n4) ? i : i - n4;
    float4 v = ((const float4*)x)[j];
    uint32_t a, b, c, d;
    split2(v.x, v.y, a, b);
    split2(v.z, v.w, c, d);
    ((uint32_t*)hh)[j * 2]     = a;
    ((uint32_t*)hh)[j * 2 + 1] = c;
    ((uint32_t*)ll)[j * 2]     = b;
    ((uint32_t*)ll)[j * 2 + 1] = d;
}

// W [K x Nc] fp32 -> WT hi/lo [Nc x K] bf16
__global__ void splitT_W(const float* __restrict__ W, int K, int Nc,
                         __nv_bfloat16* __restrict__ Thi,
                         __nv_bfloat16* __restrict__ Tlo)
{
    __shared__ float tile[32][33];
    int n0 = blockIdx.x * 32, k0 = blockIdx.y * 32;
    for (int r = threadIdx.y; r < 32; r += 8)
        tile[r][threadIdx.x] = W[(size_t)(k0 + r) * Nc + n0 + threadIdx.x];
    __syncthreads();
    for (int r = threadIdx.y; r < 32; r += 8) {
        float x = tile[threadIdx.x][r];
        __nv_bfloat16 h = __float2bfloat16(x);
        __nv_bfloat16 l = __float2bfloat16(x - __bfloat162float(h));
        size_t o = (size_t)(n0 + r) * K + k0 + threadIdx.x;
        Thi[o] = h; Tlo[o] = l;
    }
}

// ---------------------------------------------------------------------------
// GEMM tile body: C[128 x 128] = A[128 x 512] @ W^T, 3-term bf16 split,
// cp.async double-buffered. 8 warps (2m x 4n), warp tile 64x32.
// ---------------------------------------------------------------------------
#define GST 73728   // bytes per smem stage (4 buffers x 18432)

__device__ __forceinline__ void gemm_body(
    const __nv_bfloat16* __restrict__ Ahi, const __nv_bfloat16* __restrict__ Alo,
    const __nv_bfloat16* __restrict__ WThi, const __nv_bfloat16* __restrict__ WTlo,
    float* __restrict__ Cf, __nv_bfloat16* __restrict__ Chi, __nv_bfloat16* __restrict__ Clo,
    int Nc, int mode, int m0, int n0, char* smem)
{
    const uint32_t sb = smem_u32(smem);
    const int t = threadIdx.x, l = t & 31, w = t >> 5;
    const int wm = w >> 2, wn = w & 3;

    float c[4][4][4];
    #pragma unroll
    for (int i = 0; i < 4; i++)
        #pragma unroll
        for (int j = 0; j < 4; j++)
            #pragma unroll
            for (int e = 0; e < 4; e++) c[i][j][e] = 0.f;

    const int row = t >> 1, half = t & 1;
    const __nv_bfloat16* gsrc[4] = {
        Ahi  + (size_t)(m0 + row) * 512 + half * 32,
        Alo  + (size_t)(m0 + row) * 512 + half * 32,
        WThi + (size_t)(n0 + row) * 512 + half * 32,
        WTlo + (size_t)(n0 + row) * 512 + half * 32 };
    const uint32_t dbase = (uint32_t)(row * 144 + half * 64);

    // issue stage loads for k-chunk kb into stage st
    auto issue = [&](int kb, int st) {
        uint32_t so = sb + (uint32_t)st * GST + dbase;
        #pragma unroll
        for (int bufi = 0; bufi < 4; bufi++) {
            const __nv_bfloat16* s = gsrc[bufi] + kb;
            uint32_t d = so + (uint32_t)bufi * 18432;
            #pragma unroll
            for (int v = 0; v < 4; v++)
                cpa16(d + v * 16, s + v * 8);
        }
        CP_COMMIT();
    };

    issue(0, 0);

    for (int kb = 0; kb < 8; kb++) {
        const int st = kb & 1;
        if (kb < 7) { issue((kb + 1) * 64, 1 - st); CP_WAIT(1); }
        else        { CP_WAIT(0); }
        __syncthreads();

        const uint32_t sAh = sb + (uint32_t)st * GST;
        const uint32_t sAl = sAh + 18432, sWh = sAh + 36864, sWl = sAh + 55296;

        #pragma unroll
        for (int kk = 0; kk < 4; kk++) {
            uint32_t ah[4][4], al[4][4];
            #pragma unroll
            for (int i = 0; i < 4; i++) {
                ldsm4(ah[i], addrA(sAh, wm * 64 + i * 16, kk * 16, l));
                ldsm4(al[i], addrA(sAl, wm * 64 + i * 16, kk * 16, l));
            }
            #pragma unroll
            for (int p = 0; p < 2; p++) {
                uint32_t bh[4], bl[4];
                ldsm4(bh, addrB(sWh, wn * 32 + p * 16, kk * 16, l));
                ldsm4(bl, addrB(sWl, wn * 32 + p * 16, kk * 16, l));
                #pragma unroll
                for (int i = 0; i < 4; i++) {
                    #pragma unroll
                    for (int q = 0; q < 2; q++) {
                        float* acc = c[i][p * 2 + q];
                        mma16816(acc, ah[i], bh + q * 2);
                        mma16816(acc, ah[i], bl + q * 2);
                        mma16816(acc, al[i], bh + q * 2);
                    }
                }
            }
        }
        __syncthreads();
    }

    #pragma unroll
    for (int i = 0; i < 4; i++) {
        #pragma unroll
        for (int jn = 0; jn < 4; jn++) {
            int r0 = m0 + wm * 64 + i * 16 + (l >> 2);
            int cc = n0 + wn * 32 + jn * 8 + (l & 3) * 2;
            float* acc = c[i][jn];
            if (mode == 0) {
                *(float2*)(Cf + (size_t)r0 * Nc + cc)       = make_float2(acc[0], acc[1]);
                *(float2*)(Cf + (size_t)(r0 + 8) * Nc + cc) = make_float2(acc[2], acc[3]);
            } else {
                uint32_t h0, l0, h1, l1;
                split2(acc[0], acc[1], h0, l0);
                split2(acc[2], acc[3], h1, l1);
                *(uint32_t*)(Chi + (size_t)r0 * Nc + cc)       = h0;
                *(uint32_t*)(Clo + (size_t)r0 * Nc + cc)       = l0;
                *(uint32_t*)(Chi + (size_t)(r0 + 8) * Nc + cc) = h1;
                *(uint32_t*)(Clo + (size_t)(r0 + 8) * Nc + cc) = l1;
            }
        }
    }
}

// Fused Q + KV projections: grid (12, 64). bx<4 -> Q (Nc=512), else KV (Nc=1024).
__global__ __launch_bounds__(256, 1)
void proj_qkv(const __nv_bfloat16* __restrict__ curhi, const __nv_bfloat16* __restrict__ curlo,
              const __nv_bfloat16* __restrict__ hidhi, const __nv_bfloat16* __restrict__ hidlo,
              const __nv_bfloat16* __restrict__ wqThi, const __nv_bfloat16* __restrict__ wqTlo,
              const __nv_bfloat16* __restrict__ wkvThi, const __nv_bfloat16* __restrict__ wkvTlo,
              __nv_bfloat16* __restrict__ qhi, __nv_bfloat16* __restrict__ qlo,
              __nv_bfloat16* __restrict__ kvhi, __nv_bfloat16* __restrict__ kvlo)
{
    extern __shared__ __align__(1024) char smem[];
    int bx = blockIdx.x, m0 = blockIdx.y * 128;
    if (bx < 4)
        gemm_body(curhi, curlo, wqThi, wqTlo, nullptr, qhi, qlo, 512, 1,
                  m0, bx * 128, smem);
    else
        gemm_body(hidhi, hidlo, wkvThi, wkvTlo, nullptr, kvhi, kvlo, 1024, 1,
                  m0, (bx - 4) * 128, smem);
}

__global__ __launch_bounds__(256, 1)
void proj_out(const __nv_bfloat16* __restrict__ aohi, const __nv_bfloat16* __restrict__ aolo,
              const __nv_bfloat16* __restrict__ woThi, const __nv_bfloat16* __restrict__ woTlo,
              float* __restrict__ out)
{
    extern __shared__ __align__(1024) char smem[];
    gemm_body(aohi, aolo, woThi, woTlo, out, nullptr, nullptr, 512, 0,
              blockIdx.y * 128, blockIdx.x * 128, smem);
}

// ---------------------------------------------------------------------------
// Attention (no-max softmax; reference applies NO 1/sqrt(d) scale).
// Block = (b,h) x 128 q-rows, 8 warps, warp = 16 q-rows. Q fragments hoisted
// to registers; KV tiles cp.async double-buffered.
// ---------------------------------------------------------------------------
#define KVST 36864   // bytes per KV stage (Kh,Kl,Vh,Vl x 9216)

__global__ __launch_bounds__(256, 1)
void attn_mma(const __nv_bfloat16* __restrict__ Qhi, const __nv_bfloat16* __restrict__ Qlo,
              const __nv_bfloat16* __restrict__ KVhi, const __nv_bfloat16* __restrict__ KVlo,
              __nv_bfloat16* __restrict__ AOhi, __nv_bfloat16* __restrict__ AOlo)
{
    extern __shared__ __align__(1024) char smem[];
    const uint32_t sb = smem_u32(smem);
    const uint32_t sQh = sb, sQl = sb + 18432;

    const int t = threadIdx.x, l = t & 31, w = t >> 5;
    const int b = blockIdx.x >> 3, h = blockIdx.x & 7;
    const int q0 = blockIdx.y * 128;

    // ---- KV staging setup: sub 0:Khi 1:Klo 2:Vhi 3:Vlo ; jrow = t&63 ----
    const int sub = t >> 6, jrow = t & 63;
    const __nv_bfloat16* gkv = ((sub & 1) ? KVlo : KVhi)
        + (size_t)(b * N_) * 1024 + ((sub >> 1) ? 512 : 0) + h * 64;
    const uint32_t dkv = (uint32_t)(36864 + sub * 9216 + jrow * 144);

    auto issue_kv = [&](int kt, int st) {
        const __nv_bfloat16* src = gkv + (size_t)(kt * 64 + jrow) * 1024;
        uint32_t d = sb + dkv + (uint32_t)st * KVST;
        #pragma unroll
        for (int v = 0; v < 8; v++)
            cpa16(d + v * 16, src + v * 8);
        CP_COMMIT();
    };

    issue_kv(0, 0);

    // ---- stage Q tile, then hoist fragments to registers ----
    {
        const int row = t >> 1, half = t & 1;
        const __nv_bfloat16* gh = Qhi + (size_t)(b * N_ + q0 + row) * 512 + h * 64 + half * 32;
        const __nv_bfloat16* gl = Qlo + (size_t)(b * N_ + q0 + row) * 512 + h * 64 + half * 32;
        char* dh = smem +         row * 144 + half * 64;
        char* dl = smem + 18432 + row * 144 + half * 64;
        #pragma unroll
        for (int v = 0; v < 4; v++) {
            ((uint4*)dh)[v] = ((const uint4*)gh)[v];
            ((uint4*)dl)[v] = ((const uint4*)gl)[v];
        }
    }
    __syncthreads();
    uint32_t qh[4][4], ql[4][4];
    #pragma unroll
    for (int kk = 0; kk < 4; kk++) {
        ldsm4(qh[kk], addrA(sQh, w * 16, kk * 16, l));
        ldsm4(ql[kk], addrA(sQl, w * 16, kk * 16, l));
    }

    float o[8][4];
    #pragma unroll
    for (int i = 0; i < 8; i++)
        #pragma unroll
        for (int e = 0; e < 4; e++) o[i][e] = 0.f;
    float lsum0 = 0.f, lsum1 = 0.f;

    for (int kt = 0; kt < 16; kt++) {
        const int st = kt & 1;
        if (kt < 15) { issue_kv(kt + 1, 1 - st); CP_WAIT(1); }
        else         { CP_WAIT(0); }
        __syncthreads();

        const uint32_t sKh = sb + 36864 + (uint32_t)st * KVST;
        const uint32_t sKl = sKh + 9216, sVh = sKh + 18432, sVl = sKh + 27648;

        // ---- S = Q K^T ----
        float s[8][4];
        #pragma unroll
        for (int i = 0; i < 8; i++)
            #pragma unroll
            for (int e = 0; e < 4; e++) s[i][e] = 0.f;

        #pragma unroll
        for (int kk = 0; kk < 4; kk++) {
            #pragma unroll
            for (int p = 0; p < 4; p++) {
                uint32_t bh[4], bl[4];
                ldsm4(bh, addrB(sKh, p * 16, kk * 16, l));
                ldsm4(bl, addrB(sKl, p * 16, kk * 16, l));
                #pragma unroll
                for (int q = 0; q < 2; q++) {
                    float* acc = s[p * 2 + q];
                    mma16816(acc, qh[kk], bh + q * 2);
                    mma16816(acc, qh[kk], bl + q * 2);
                    mma16816(acc, ql[kk], bh + q * 2);
                }
            }
        }

        // ---- exp + row sums + pack P into A-fragments ----
        uint32_t pa_h[4][4], pa_l[4][4];
        #pragma unroll
        for (int jn = 0; jn < 8; jn++) {
            float e0 = __expf(s[jn][0]);
            float e1 = __expf(s[jn][1]);
            float e2 = __expf(s[jn][2]);
            float e3 = __expf(s[jn][3]);
            lsum0 += e0 + e1;
            lsum1 += e2 + e3;
            int kj = jn >> 1, base = (jn & 1) * 2;
            split2(e0, e1, pa_h[kj][base + 0], pa_l[kj][base + 0]);
            split2(e2, e3, pa_h[kj][base + 1], pa_l[kj][base + 1]);
        }

        // ---- O += P V ----
        #pragma unroll
        for (int kj = 0; kj < 4; kj++) {
            #pragma unroll
            for (int pd = 0; pd < 4; pd++) {
                uint32_t bh[4], bl[4];
                uint32_t va = (uint32_t)((kj * 16 + ((l >> 3) & 1) * 8 + (l & 7)) * 144
                                         + (pd * 16 + ((l >> 4) & 1) * 8) * 2);
                ldsm4t(bh, sVh + va);
                ldsm4t(bl, sVl + va);
                #pragma unroll
                for (int q = 0; q < 2; q++) {
                    float* acc = o[pd * 2 + q];
                    mma16816(acc, pa_h[kj], bh + q * 2);
                    mma16816(acc, pa_h[kj], bl + q * 2);
                    mma16816(acc, pa_l[kj], bh + q * 2);
                }
            }
        }
        __syncthreads();
    }

    lsum0 += __shfl_xor_sync(0xffffffffu, lsum0, 1);
    lsum0 += __shfl_xor_sync(0xffffffffu, lsum0, 2);
    lsum1 += __shfl_xor_sync(0xffffffffu, lsum1, 1);
    lsum1 += __shfl_xor_sync(0xffffffffu, lsum1, 2);
    float inv0 = 1.f / lsum0, inv1 = 1.f / lsum1;

    const int rowg = b * N_ + q0 + w * 16 + (l >> 2);
    #pragma unroll
    for (int dn = 0; dn < 8; dn++) {
        int cc = h * 64 + dn * 8 + (l & 3) * 2;
        uint32_t h0, l0, h1, l1;
        split2(o[dn][0] * inv0, o[dn][1] * inv0, h0, l0);
        split2(o[dn][2] * inv1, o[dn][3] * inv1, h1, l1);
        *(uint32_t*)(AOhi + (size_t)rowg * 512 + cc)       = h0;
        *(uint32_t*)(AOlo + (size_t)rowg * 512 + cc)       = l0;
        *(uint32_t*)(AOhi + (size_t)(rowg + 8) * 512 + cc) = h1;
        *(uint32_t*)(AOlo + (size_t)(rowg + 8) * 512 + cc) = l1;
    }
}

// ---------------------------------------------------------------------------
extern "C" void kernel_launch(void* const* d_in, const int* in_sizes, int n_in,
                              void* d_out, int out_size)
{
    (void)in_sizes; (void)n_in; (void)out_size;
    const float* current = (const float*)d_in[0];
    const float* hidden  = (const float*)d_in[1];
    const float* Wq      = (const float*)d_in[2];
    const float* Wkv     = (const float*)d_in[3];
    const float* Wo      = (const float*)d_in[4];
    float* out           = (float*)d_out;

    __nv_bfloat16 *curhi, *curlo, *hidhi, *hidlo;
    __nv_bfloat16 *wqThi, *wqTlo, *wkvThi, *wkvTlo, *woThi, *woTlo;
    __nv_bfloat16 *qhi, *qlo, *kvhi, *kvlo, *aohi, *aolo;
    cudaGetSymbolAddress((void**)&curhi,  g_curhi);  cudaGetSymbolAddress((void**)&curlo,  g_curlo);
    cudaGetSymbolAddress((void**)&hidhi,  g_hidhi);  cudaGetSymbolAddress((void**)&hidlo,  g_hidlo);
    cudaGetSymbolAddress((void**)&wqThi,  g_wqThi);  cudaGetSymbolAddress((void**)&wqTlo,  g_wqTlo);
    cudaGetSymbolAddress((void**)&wkvThi, g_wkvThi); cudaGetSymbolAddress((void**)&wkvTlo, g_wkvTlo);
    cudaGetSymbolAddress((void**)&woThi,  g_woThi);  cudaGetSymbolAddress((void**)&woTlo,  g_woTlo);
    cudaGetSymbolAddress((void**)&qhi,  g_qhi);   cudaGetSymbolAddress((void**)&qlo,  g_qlo);
    cudaGetSymbolAddress((void**)&kvhi, g_kvhi);  cudaGetSymbolAddress((void**)&kvlo, g_kvlo);
    cudaGetSymbolAddress((void**)&aohi, g_aohi);  cudaGetSymbolAddress((void**)&aolo, g_aolo);

    const int gemm_smem = 2 * GST;                 // 147456
    const int attn_smem = 36864 + 2 * KVST;        // 110592
    cudaFuncSetAttribute(proj_qkv, cudaFuncAttributeMaxDynamicSharedMemorySize, gemm_smem);
    cudaFuncSetAttribute(proj_out, cudaFuncAttributeMaxDynamicSharedMemorySize, gemm_smem);
    cudaFuncSetAttribute(attn_mma, cudaFuncAttributeMaxDynamicSharedMemorySize, attn_smem);

    const int n4 = MT_ * DM_ / 4;
    split_two<<<2 * n4 / 256, 256>>>(current, hidden, curhi, curlo, hidhi, hidlo, n4);
    splitT_W<<<dim3(DM_ / 32, DM_ / 32), dim3(32, 8)>>>(Wq,  DM_, DM_,     wqThi,  wqTlo);
    splitT_W<<<dim3(2 * DM_ / 32, DM_ / 32), dim3(32, 8)>>>(Wkv, DM_, 2 * DM_, wkvThi, wkvTlo);
    splitT_W<<<dim3(DM_ / 32, DM_ / 32), dim3(32, 8)>>>(Wo,  DM_, DM_,     woThi,  woTlo);

    proj_qkv<<<dim3(12, 64), 256, gemm_smem>>>(curhi, curlo, hidhi, hidlo,
                                               wqThi, wqTlo, wkvThi, wkvTlo,
                                               qhi, qlo, kvhi, kvlo);
    attn_mma<<<dim3(B_ * H_, N_ / 128), 256, attn_smem>>>(qhi, qlo, kvhi, kvlo, aohi, aolo);
    proj_out<<<dim3(4, 64), 256, gemm_smem>>>(aohi, aolo, woThi, woTlo, out);
}

// round 8
// speedup vs baseline: 1.1279x; 1.1279x over previous
#include <cuda_runtime.h>
#include <cuda_fp16.h>
#include <cstdint>
#include <math.h>

#define B_   8
#define N_   1024
#define DM_  512
#define H_   8
#define MT_  (B_ * N_)      // 8192
#define GB   18432          // 128 rows x 144 B smem buffer

// ---------------- fp16 scratch (__device__ globals; no allocs) -------------
__device__ __half g_curhi[MT_ * DM_], g_curlo[MT_ * DM_];
__device__ __half g_hidhi[MT_ * DM_], g_hidlo[MT_ * DM_];
__device__ __half g_wqThi [DM_ * DM_],     g_wqTlo [DM_ * DM_];
__device__ __half g_wkvThi[2 * DM_ * DM_], g_wkvTlo[2 * DM_ * DM_];
__device__ __half g_woT   [DM_ * DM_];
__device__ __half g_qhi[MT_ * DM_], g_qlo[MT_ * DM_];
__device__ __half g_khi[MT_ * DM_], g_klo[MT_ * DM_];
__device__ __half g_v  [MT_ * DM_];
__device__ __half g_aohi[MT_ * DM_], g_aolo[MT_ * DM_];

// ---------------- helpers ---------------------------------------------------
__device__ __forceinline__ uint32_t smem_u32(const void* p) {
    uint32_t a;
    asm("{ .reg .u64 t; cvta.to.shared.u64 t, %1; cvt.u32.u64 %0, t; }" : "=r"(a) : "l"(p));
    return a;
}
__device__ __forceinline__ void cpa16(uint32_t dst, const void* src) {
    asm volatile("cp.async.cg.shared.global [%0], [%1], 16;" :: "r"(dst), "l"(src));
}
#define CP_COMMIT() asm volatile("cp.async.commit_group;" ::: "memory")
#define CP_WAIT0()  asm volatile("cp.async.wait_group 0;" ::: "memory")

__device__ __forceinline__ void ldsm4(uint32_t* r, uint32_t addr) {
    asm volatile("ldmatrix.sync.aligned.m8n8.x4.shared.b16 {%0,%1,%2,%3}, [%4];"
        : "=r"(r[0]), "=r"(r[1]), "=r"(r[2]), "=r"(r[3]) : "r"(addr));
}
__device__ __forceinline__ void ldsm4t(uint32_t* r, uint32_t addr) {
    asm volatile("ldmatrix.sync.aligned.m8n8.x4.trans.shared.b16 {%0,%1,%2,%3}, [%4];"
        : "=r"(r[0]), "=r"(r[1]), "=r"(r[2]), "=r"(r[3]) : "r"(addr));
}
__device__ __forceinline__ void mma16816(float* c, const uint32_t* a, const uint32_t* b) {
    asm volatile("mma.sync.aligned.m16n8k16.row.col.f32.f16.f16.f32 "
        "{%0,%1,%2,%3}, {%4,%5,%6,%7}, {%8,%9}, {%0,%1,%2,%3};"
        : "+f"(c[0]), "+f"(c[1]), "+f"(c[2]), "+f"(c[3])
        : "r"(a[0]), "r"(a[1]), "r"(a[2]), "r"(a[3]), "r"(b[0]), "r"(b[1]));
}
__device__ __forceinline__ uint32_t hpack(__half a, __half b) {
    __half2 t; t.x = a; t.y = b;
    return *(uint32_t*)&t;
}
__device__ __forceinline__ void split2h(float v0, float v1, uint32_t& hi, uint32_t& lo) {
    __half h0 = __float2half_rn(v0), h1 = __float2half_rn(v1);
    __half l0 = __float2half_rn(v0 - __half2float(h0));
    __half l1 = __float2half_rn(v1 - __half2float(h1));
    hi = hpack(h0, h1); lo = hpack(l0, l1);
}

// smem rows 144 B (72 halves) -> conflict-free ldmatrix
__device__ __forceinline__ uint32_t addrA(uint32_t base, int row, int col, int l) {
    return base + (uint32_t)((row + (l & 15)) * 144 + (col + (l >> 4) * 8) * 2);
}
__device__ __forceinline__ uint32_t addrB(uint32_t base, int row, int col, int l) {
    return base + (uint32_t)((row + ((l >> 4) & 1) * 8 + (l & 7)) * 144
                             + (col + ((l >> 3) & 1) * 8) * 2);
}

// ---------------------------------------------------------------------------
// conversions
// ---------------------------------------------------------------------------
__global__ void split_two(const float* __restrict__ x0, const float* __restrict__ x1,
                          __half* __restrict__ h0, __half* __restrict__ l0p,
                          __half* __restrict__ h1, __half* __restrict__ l1p, int n4)
{
    int i = blockIdx.x * blockDim.x + threadIdx.x;
    const float* x = (i < n4) ? x0 : x1;
    __half* hh = (i < n4) ? h0 : h1;
    __half* ll = (i < n4) ? l0p : l1p;
    int j = (i < n4) ? i : i - n4;
    float4 v = ((const float4*)x)[j];
    uint32_t a, b, c, d;
    split2h(v.x, v.y, a, b);
    split2h(v.z, v.w, c, d);
    ((uint32_t*)hh)[j * 2]     = a;
    ((uint32_t*)hh)[j * 2 + 1] = c;
    ((uint32_t*)ll)[j * 2]     = b;
    ((uint32_t*)ll)[j * 2 + 1] = d;
}

// Wq,Wkv -> 2-split fp16 transposed; Wo -> single fp16 transposed. One launch.
__global__ void cvtT_W(const float* __restrict__ Wq, const float* __restrict__ Wkv,
                       const float* __restrict__ Wo,
                       __half* __restrict__ wqThi, __half* __restrict__ wqTlo,
                       __half* __restrict__ wkvThi, __half* __restrict__ wkvTlo,
                       __half* __restrict__ woT)
{
    __shared__ float tile[32][33];
    int bx = blockIdx.x;
    const float* W; __half *Thi, *Tlo; int Nc, idx, do_split;
    if (bx < 256)      { W = Wq;  Thi = wqThi;  Tlo = wqTlo;  Nc = 512;  idx = bx;       do_split = 1; }
    else if (bx < 768) { W = Wkv; Thi = wkvThi; Tlo = wkvTlo; Nc = 1024; idx = bx - 256; do_split = 1; }
    else               { W = Wo;  Thi = woT;    Tlo = 0;      Nc = 512;  idx = bx - 768; do_split = 0; }
    int tn = Nc / 32;
    int n0 = (idx % tn) * 32, k0 = (idx / tn) * 32;
    for (int r = threadIdx.y; r < 32; r += 8)
        tile[r][threadIdx.x] = W[(size_t)(k0 + r) * Nc + n0 + threadIdx.x];
    __syncthreads();
    for (int r = threadIdx.y; r < 32; r += 8) {
        float x = tile[threadIdx.x][r];
        __half h = __float2half_rn(x);
        size_t o = (size_t)(n0 + r) * 512 + k0 + threadIdx.x;
        Thi[o] = h;
        if (do_split) Tlo[o] = __float2half_rn(x - __half2float(h));
    }
}

// ---------------------------------------------------------------------------
// GEMM tile: out[128x128] = (Ahi+Alo)[128x512] @ WT^T with 2 or 3 fp16 terms.
// 8 warps (2m x 4n), warp tile 64x32. All output arrays have row stride 512.
// mode 0: fp32 out; mode 1: fp16 2-split out; mode 2: fp16 single out.
// ---------------------------------------------------------------------------
__device__ __forceinline__ void gemm_body(
    const __half* __restrict__ Ahi, const __half* __restrict__ Alo,
    const __half* __restrict__ WThi, const __half* __restrict__ WTlo,
    int m0, int n0w, int n0out, int terms, int mode,
    float* __restrict__ outf, __half* __restrict__ outhi, __half* __restrict__ outlo,
    char* smem)
{
    const uint32_t sb = smem_u32(smem);
    const int t = threadIdx.x, l = t & 31, w = t >> 5;
    const int wm = w >> 2, wn = w & 3;
    const uint32_t sAh = sb, sAl = sb + GB, sWh = sb + 2 * GB, sWl = sb + 3 * GB;

    float c[4][4][4];
    #pragma unroll
    for (int i = 0; i < 4; i++)
        #pragma unroll
        for (int j = 0; j < 4; j++)
            #pragma unroll
            for (int e = 0; e < 4; e++) c[i][j][e] = 0.f;

    const int row = t >> 1, half = t & 1;
    const __half* gAh = Ahi  + (size_t)(m0 + row) * 512 + half * 32;
    const __half* gAl = Alo  + (size_t)(m0 + row) * 512 + half * 32;
    const __half* gWh = WThi + (size_t)(n0w + row) * 512 + half * 32;
    const __half* gWl = terms == 3 ? WTlo + (size_t)(n0w + row) * 512 + half * 32 : gWh;
    const uint32_t db = (uint32_t)(row * 144 + half * 64);

    for (int kb = 0; kb < 512; kb += 64) {
        #pragma unroll
        for (int v = 0; v < 4; v++) {
            cpa16(sAh + db + v * 16, gAh + kb + v * 8);
            cpa16(sAl + db + v * 16, gAl + kb + v * 8);
            cpa16(sWh + db + v * 16, gWh + kb + v * 8);
        }
        if (terms == 3) {
            #pragma unroll
            for (int v = 0; v < 4; v++)
                cpa16(sWl + db + v * 16, gWl + kb + v * 8);
        }
        CP_COMMIT();
        CP_WAIT0();
        __syncthreads();

        #pragma unroll
        for (int kk = 0; kk < 4; kk++) {
            uint32_t ah[4][4], al[4][4];
            #pragma unroll
            for (int i = 0; i < 4; i++) {
                ldsm4(ah[i], addrA(sAh, wm * 64 + i * 16, kk * 16, l));
                ldsm4(al[i], addrA(sAl, wm * 64 + i * 16, kk * 16, l));
            }
            #pragma unroll
            for (int p = 0; p < 2; p++) {
                uint32_t bh[4], bl[4];
                ldsm4(bh, addrB(sWh, wn * 32 + p * 16, kk * 16, l));
                if (terms == 3) ldsm4(bl, addrB(sWl, wn * 32 + p * 16, kk * 16, l));
                #pragma unroll
                for (int i = 0; i < 4; i++) {
                    #pragma unroll
                    for (int q = 0; q < 2; q++) {
                        float* acc = c[i][p * 2 + q];
                        mma16816(acc, ah[i], bh + q * 2);
                        mma16816(acc, al[i], bh + q * 2);
                        if (terms == 3) mma16816(acc, ah[i], bl + q * 2);
                    }
                }
            }
        }
        __syncthreads();
    }

    #pragma unroll
    for (int i = 0; i < 4; i++) {
        #pragma unroll
        for (int jn = 0; jn < 4; jn++) {
            int r0 = m0 + wm * 64 + i * 16 + (l >> 2);
            int cc = n0out + wn * 32 + jn * 8 + (l & 3) * 2;
            float* acc = c[i][jn];
            if (mode == 0) {
                *(float2*)(outf + (size_t)r0 * 512 + cc)       = make_float2(acc[0], acc[1]);
                *(float2*)(outf + (size_t)(r0 + 8) * 512 + cc) = make_float2(acc[2], acc[3]);
            } else if (mode == 1) {
                uint32_t h0, l0, h1, l1;
                split2h(acc[0], acc[1], h0, l0);
                split2h(acc[2], acc[3], h1, l1);
                *(uint32_t*)(outhi + (size_t)r0 * 512 + cc)       = h0;
                *(uint32_t*)(outlo + (size_t)r0 * 512 + cc)       = l0;
                *(uint32_t*)(outhi + (size_t)(r0 + 8) * 512 + cc) = h1;
                *(uint32_t*)(outlo + (size_t)(r0 + 8) * 512 + cc) = l1;
            } else {
                *(uint32_t*)(outhi + (size_t)r0 * 512 + cc) =
                    hpack(__float2half_rn(acc[0]), __float2half_rn(acc[1]));
                *(uint32_t*)(outhi + (size_t)(r0 + 8) * 512 + cc) =
                    hpack(__float2half_rn(acc[2]), __float2half_rn(acc[3]));
            }
        }
    }
}

// grid (12, 64): bx 0-3 Q (3-term, split out), 4-7 K (3-term, split out),
// 8-11 V (2-term, single out)
__global__ __launch_bounds__(256)
void proj_qkv(const __half* __restrict__ curhi, const __half* __restrict__ curlo,
              const __half* __restrict__ hidhi, const __half* __restrict__ hidlo,
              const __half* __restrict__ wqThi, const __half* __restrict__ wqTlo,
              const __half* __restrict__ wkvThi, const __half* __restrict__ wkvTlo,
              __half* __restrict__ qhi, __half* __restrict__ qlo,
              __half* __restrict__ khi, __half* __restrict__ klo,
              __half* __restrict__ vv)
{
    extern __shared__ __align__(1024) char smem[];
    int bx = blockIdx.x, m0 = blockIdx.y * 128;
    if (bx < 4)
        gemm_body(curhi, curlo, wqThi, wqTlo, m0, bx * 128, bx * 128, 3, 1,
                  nullptr, qhi, qlo, smem);
    else if (bx < 8)
        gemm_body(hidhi, hidlo, wkvThi, wkvTlo, m0, (bx - 4) * 128, (bx - 4) * 128,
                  3, 1, nullptr, khi, klo, smem);
    else
        gemm_body(hidhi, hidlo, wkvThi, wkvTlo, m0, 512 + (bx - 8) * 128,
                  (bx - 8) * 128, 2, 2, nullptr, vv, nullptr, smem);
}

__global__ __launch_bounds__(256)
void proj_out(const __half* __restrict__ aohi, const __half* __restrict__ aolo,
              const __half* __restrict__ woT, float* __restrict__ out)
{
    extern __shared__ __align__(1024) char smem[];
    gemm_body(aohi, aolo, woT, nullptr, blockIdx.y * 128, blockIdx.x * 128,
              blockIdx.x * 128, 2, 0, out, nullptr, nullptr, smem);
}

// ---------------------------------------------------------------------------
// Attention, online-max softmax (NO 1/sqrt(d) scale per reference).
// Block = (b,h) x 128 q-rows, 8 warps x 16 q-rows.
// S: Q 2-split x K 2-split, 3 terms. P: fp16 2-split of exp(s - m) in [0,1].
// PV: 2 terms (P split x V single fp16).
// ---------------------------------------------------------------------------
__global__ __launch_bounds__(256)
void attn_mma(const __half* __restrict__ Qhi, const __half* __restrict__ Qlo,
              const __half* __restrict__ Khi, const __half* __restrict__ Klo,
              const __half* __restrict__ Vv,
              __half* __restrict__ AOhi, __half* __restrict__ AOlo)
{
    extern __shared__ __align__(1024) char smem[];
    const uint32_t sb = smem_u32(smem);
    const uint32_t sQh = sb, sQl = sb + GB;
    const uint32_t sKh = sb + 2 * GB;
    const uint32_t sKl = sKh + 9216;
    const uint32_t sV  = sKl + 9216;

    const int t = threadIdx.x, l = t & 31, w = t >> 5;
    const int b = blockIdx.x >> 3, h = blockIdx.x & 7;
    const int q0 = blockIdx.y * 128;

    // stage resident Q tile
    {
        const int row = t >> 1, half = t & 1;
        const __half* gh = Qhi + (size_t)(b * N_ + q0 + row) * 512 + h * 64 + half * 32;
        const __half* gl = Qlo + (size_t)(b * N_ + q0 + row) * 512 + h * 64 + half * 32;
        char* dh = smem +      row * 144 + half * 64;
        char* dl = smem + GB + row * 144 + half * 64;
        #pragma unroll
        for (int v = 0; v < 4; v++) {
            ((uint4*)dh)[v] = ((const uint4*)gh)[v];
            ((uint4*)dl)[v] = ((const uint4*)gl)[v];
        }
    }
    __syncthreads();
    uint32_t qh[4][4], ql[4][4];
    #pragma unroll
    for (int kk = 0; kk < 4; kk++) {
        ldsm4(qh[kk], addrA(sQh, w * 16, kk * 16, l));
        ldsm4(ql[kk], addrA(sQl, w * 16, kk * 16, l));
    }

    float o[8][4];
    #pragma unroll
    for (int i = 0; i < 8; i++)
        #pragma unroll
        for (int e = 0; e < 4; e++) o[i][e] = 0.f;
    float lsum0 = 0.f, lsum1 = 0.f;
    float m0r = -1e30f, m1r = -1e30f;

    for (int kt = 0; kt < 16; kt++) {
        // stage Khi/Klo/V tiles (3 x 64 rows x 128 B); 384 tasks over 256 thr
        for (int i = t; i < 384; i += 256) {
            int buf = i >> 7, rr = (i & 127) >> 1, hf = i & 1;
            const __half* base = (buf == 0) ? Khi : (buf == 1) ? Klo : Vv;
            const __half* src = base + (size_t)(b * N_ + kt * 64 + rr) * 512
                                + h * 64 + hf * 32;
            uint32_t d = ((buf == 0) ? sKh : (buf == 1) ? sKl : sV)
                         + (uint32_t)(rr * 144 + hf * 64);
            #pragma unroll
            for (int v = 0; v < 4; v++)
                cpa16(d + v * 16, src + v * 8);
        }
        CP_COMMIT();
        CP_WAIT0();
        __syncthreads();

        // ---- S = Q K^T (3 terms) ----
        float s[8][4];
        #pragma unroll
        for (int i = 0; i < 8; i++)
            #pragma unroll
            for (int e = 0; e < 4; e++) s[i][e] = 0.f;

        #pragma unroll
        for (int kk = 0; kk < 4; kk++) {
            #pragma unroll
            for (int p = 0; p < 4; p++) {
                uint32_t bh[4], bl[4];
                ldsm4(bh, addrB(sKh, p * 16, kk * 16, l));
                ldsm4(bl, addrB(sKl, p * 16, kk * 16, l));
                #pragma unroll
                for (int q = 0; q < 2; q++) {
                    float* acc = s[p * 2 + q];
                    mma16816(acc, qh[kk], bh + q * 2);
                    mma16816(acc, ql[kk], bh + q * 2);
                    mma16816(acc, qh[kk], bl + q * 2);
                }
            }
        }

        // ---- online max over this tile's rows ----
        float rm0 = -1e30f, rm1 = -1e30f;
        #pragma unroll
        for (int jn = 0; jn < 8; jn++) {
            rm0 = fmaxf(rm0, fmaxf(s[jn][0], s[jn][1]));
            rm1 = fmaxf(rm1, fmaxf(s[jn][2], s[jn][3]));
        }
        rm0 = fmaxf(rm0, __shfl_xor_sync(0xffffffffu, rm0, 1));
        rm0 = fmaxf(rm0, __shfl_xor_sync(0xffffffffu, rm0, 2));
        rm1 = fmaxf(rm1, __shfl_xor_sync(0xffffffffu, rm1, 1));
        rm1 = fmaxf(rm1, __shfl_xor_sync(0xffffffffu, rm1, 2));
        float m0n = fmaxf(m0r, rm0), m1n = fmaxf(m1r, rm1);
        float sc0 = __expf(m0r - m0n), sc1 = __expf(m1r - m1n);
        m0r = m0n; m1r = m1n;
        lsum0 *= sc0; lsum1 *= sc1;
        #pragma unroll
        for (int i = 0; i < 8; i++) {
            o[i][0] *= sc0; o[i][1] *= sc0;
            o[i][2] *= sc1; o[i][3] *= sc1;
        }

        // ---- exp + row sums + pack P (fp16 2-split, values in [0,1]) ----
        uint32_t pa_h[4][4], pa_l[4][4];
        #pragma unroll
        for (int jn = 0; jn < 8; jn++) {
            float e0 = __expf(s[jn][0] - m0r);
            float e1 = __expf(s[jn][1] - m0r);
            float e2 = __expf(s[jn][2] - m1r);
            float e3 = __expf(s[jn][3] - m1r);
            lsum0 += e0 + e1;
            lsum1 += e2 + e3;
            int kj = jn >> 1, base = (jn & 1) * 2;
            split2h(e0, e1, pa_h[kj][base + 0], pa_l[kj][base + 0]);
            split2h(e2, e3, pa_h[kj][base + 1], pa_l[kj][base + 1]);
        }

        // ---- O += P V (2 terms) ----
        #pragma unroll
        for (int kj = 0; kj < 4; kj++) {
            #pragma unroll
            for (int pd = 0; pd < 4; pd++) {
                uint32_t bv[4];
                uint32_t va = (uint32_t)((kj * 16 + ((l >> 3) & 1) * 8 + (l & 7)) * 144
                                         + (pd * 16 + ((l >> 4) & 1) * 8) * 2);
                ldsm4t(bv, sV + va);
                #pragma unroll
                for (int q = 0; q < 2; q++) {
                    float* acc = o[pd * 2 + q];
                    mma16816(acc, pa_h[kj], bv + q * 2);
                    mma16816(acc, pa_l[kj], bv + q * 2);
                }
            }
        }
        __syncthreads();
    }

    lsum0 += __shfl_xor_sync(0xffffffffu, lsum0, 1);
    lsum0 += __shfl_xor_sync(0xffffffffu, lsum0, 2);
    lsum1 += __shfl_xor_sync(0xffffffffu, lsum1, 1);
    lsum1 += __shfl_xor_sync(0xffffffffu, lsum1, 2);
    float inv0 = 1.f / lsum0, inv1 = 1.f / lsum1;

    const int rowg = b * N_ + q0 + w * 16 + (l >> 2);
    #pragma unroll
    for (int dn = 0; dn < 8; dn++) {
        int cc = h * 64 + dn * 8 + (l & 3) * 2;
        uint32_t h0, l0, h1, l1;
        split2h(o[dn][0] * inv0, o[dn][1] * inv0, h0, l0);
        split2h(o[dn][2] * inv1, o[dn][3] * inv1, h1, l1);
        *(uint32_t*)(AOhi + (size_t)rowg * 512 + cc)       = h0;
        *(uint32_t*)(AOlo + (size_t)rowg * 512 + cc)       = l0;
        *(uint32_t*)(AOhi + (size_t)(rowg + 8) * 512 + cc) = h1;
        *(uint32_t*)(AOlo + (size_t)(rowg + 8) * 512 + cc) = l1;
    }
}

// ---------------------------------------------------------------------------
extern "C" void kernel_launch(void* const* d_in, const int* in_sizes, int n_in,
                              void* d_out, int out_size)
{
    (void)in_sizes; (void)n_in; (void)out_size;
    const float* current = (const float*)d_in[0];
    const float* hidden  = (const float*)d_in[1];
    const float* Wq      = (const float*)d_in[2];
    const float* Wkv     = (const float*)d_in[3];
    const float* Wo      = (const float*)d_in[4];
    float* out           = (float*)d_out;

    __half *curhi, *curlo, *hidhi, *hidlo;
    __half *wqThi, *wqTlo, *wkvThi, *wkvTlo, *woT;
    __half *qhi, *qlo, *khi, *klo, *vv, *aohi, *aolo;
    cudaGetSymbolAddress((void**)&curhi, g_curhi); cudaGetSymbolAddress((void**)&curlo, g_curlo);
    cudaGetSymbolAddress((void**)&hidhi, g_hidhi); cudaGetSymbolAddress((void**)&hidlo, g_hidlo);
    cudaGetSymbolAddress((void**)&wqThi, g_wqThi); cudaGetSymbolAddress((void**)&wqTlo, g_wqTlo);
    cudaGetSymbolAddress((void**)&wkvThi, g_wkvThi); cudaGetSymbolAddress((void**)&wkvTlo, g_wkvTlo);
    cudaGetSymbolAddress((void**)&woT, g_woT);
    cudaGetSymbolAddress((void**)&qhi, g_qhi);   cudaGetSymbolAddress((void**)&qlo, g_qlo);
    cudaGetSymbolAddress((void**)&khi, g_khi);   cudaGetSymbolAddress((void**)&klo, g_klo);
    cudaGetSymbolAddress((void**)&vv,  g_v);
    cudaGetSymbolAddress((void**)&aohi, g_aohi); cudaGetSymbolAddress((void**)&aolo, g_aolo);

    const int gemm_smem = 4 * GB;                    // 73728
    const int attn_smem = 2 * GB + 3 * 9216;         // 64512
    cudaFuncSetAttribute(proj_qkv, cudaFuncAttributeMaxDynamicSharedMemorySize, gemm_smem);
    cudaFuncSetAttribute(proj_out, cudaFuncAttributeMaxDynamicSharedMemorySize, gemm_smem);
    cudaFuncSetAttribute(attn_mma, cudaFuncAttributeMaxDynamicSharedMemorySize, attn_smem);

    const int n4 = MT_ * DM_ / 4;
    split_two<<<2 * n4 / 256, 256>>>(current, hidden, curhi, curlo, hidhi, hidlo, n4);
    cvtT_W<<<1024, dim3(32, 8)>>>(Wq, Wkv, Wo, wqThi, wqTlo, wkvThi, wkvTlo, woT);

    proj_qkv<<<dim3(12, 64), 256, gemm_smem>>>(curhi, curlo, hidhi, hidlo,
                                               wqThi, wqTlo, wkvThi, wkvTlo,
                                               qhi, qlo, khi, klo, vv);
    attn_mma<<<dim3(B_ * H_, N_ / 128), 256, attn_smem>>>(qhi, qlo, khi, klo, vv,
                                                          aohi, aolo);
    proj_out<<<dim3(4, 64), 256, gemm_smem>>>(aohi, aolo, woT, out);
}

// round 9
// speedup vs baseline: 1.3133x; 1.1644x over previous
#include <cuda_runtime.h>
#include <cuda_fp16.h>
#include <cstdint>
#include <math.h>

#define B_   8
#define N_   1024
#define DM_  512
#define H_   8
#define MT_  (B_ * N_)      // 8192
#define GB   18432          // 128 rows x 144 B smem buffer

// ---------------- fp16 scratch (__device__ globals; no allocs) -------------
__device__ __half g_curhi[MT_ * DM_], g_curlo[MT_ * DM_];
__device__ __half g_hidhi[MT_ * DM_], g_hidlo[MT_ * DM_];
__device__ __half g_wqThi [DM_ * DM_],     g_wqTlo [DM_ * DM_];
__device__ __half g_wkvThi[2 * DM_ * DM_], g_wkvTlo[2 * DM_ * DM_];
__device__ __half g_woT   [DM_ * DM_];
__device__ __half g_qhi[MT_ * DM_], g_qlo[MT_ * DM_];
__device__ __half g_khi[MT_ * DM_], g_klo[MT_ * DM_];
__device__ __half g_v  [MT_ * DM_];
__device__ __half g_aohi[MT_ * DM_], g_aolo[MT_ * DM_];

// ---------------- helpers ---------------------------------------------------
__device__ __forceinline__ uint32_t smem_u32(const void* p) {
    uint32_t a;
    asm("{ .reg .u64 t; cvta.to.shared.u64 t, %1; cvt.u32.u64 %0, t; }" : "=r"(a) : "l"(p));
    return a;
}
__device__ __forceinline__ void cpa16(uint32_t dst, const void* src) {
    asm volatile("cp.async.cg.shared.global [%0], [%1], 16;" :: "r"(dst), "l"(src));
}
#define CP_COMMIT() asm volatile("cp.async.commit_group;" ::: "memory")
#define CP_WAIT0()  asm volatile("cp.async.wait_group 0;" ::: "memory")

__device__ __forceinline__ void ldsm4(uint32_t* r, uint32_t addr) {
    asm volatile("ldmatrix.sync.aligned.m8n8.x4.shared.b16 {%0,%1,%2,%3}, [%4];"
        : "=r"(r[0]), "=r"(r[1]), "=r"(r[2]), "=r"(r[3]) : "r"(addr));
}
__device__ __forceinline__ void ldsm4t(uint32_t* r, uint32_t addr) {
    asm volatile("ldmatrix.sync.aligned.m8n8.x4.trans.shared.b16 {%0,%1,%2,%3}, [%4];"
        : "=r"(r[0]), "=r"(r[1]), "=r"(r[2]), "=r"(r[3]) : "r"(addr));
}
__device__ __forceinline__ void mma16816(float* c, const uint32_t* a, const uint32_t* b) {
    asm volatile("mma.sync.aligned.m16n8k16.row.col.f32.f16.f16.f32 "
        "{%0,%1,%2,%3}, {%4,%5,%6,%7}, {%8,%9}, {%0,%1,%2,%3};"
        : "+f"(c[0]), "+f"(c[1]), "+f"(c[2]), "+f"(c[3])
        : "r"(a[0]), "r"(a[1]), "r"(a[2]), "r"(a[3]), "r"(b[0]), "r"(b[1]));
}
__device__ __forceinline__ uint32_t hpack(__half a, __half b) {
    __half2 t; t.x = a; t.y = b;
    return *(uint32_t*)&t;
}
__device__ __forceinline__ void split2h(float v0, float v1, uint32_t& hi, uint32_t& lo) {
    __half h0 = __float2half_rn(v0), h1 = __float2half_rn(v1);
    __half l0 = __float2half_rn(v0 - __half2float(h0));
    __half l1 = __float2half_rn(v1 - __half2float(h1));
    hi = hpack(h0, h1); lo = hpack(l0, l1);
}

// smem rows 144 B (72 halves) -> conflict-free ldmatrix
__device__ __forceinline__ uint32_t addrA(uint32_t base, int row, int col, int l) {
    return base + (uint32_t)((row + (l & 15)) * 144 + (col + (l >> 4) * 8) * 2);
}
__device__ __forceinline__ uint32_t addrB(uint32_t base, int row, int col, int l) {
    return base + (uint32_t)((row + ((l >> 4) & 1) * 8 + (l & 7)) * 144
                             + (col + ((l >> 3) & 1) * 8) * 2);
}

// ---------------------------------------------------------------------------
// conversions
// ---------------------------------------------------------------------------
__global__ void split_two(const float* __restrict__ x0, const float* __restrict__ x1,
                          __half* __restrict__ h0, __half* __restrict__ l0p,
                          __half* __restrict__ h1, __half* __restrict__ l1p, int n4)
{
    int i = blockIdx.x * blockDim.x + threadIdx.x;
    const float* x = (i < n4) ? x0 : x1;
    __half* hh = (i < n4) ? h0 : h1;
    __half* ll = (i < n4) ? l0p : l1p;
    int j = (i < n4) ? i : i - n4;
    float4 v = ((const float4*)x)[j];
    uint32_t a, b, c, d;
    split2h(v.x, v.y, a, b);
    split2h(v.z, v.w, c, d);
    ((uint32_t*)hh)[j * 2]     = a;
    ((uint32_t*)hh)[j * 2 + 1] = c;
    ((uint32_t*)ll)[j * 2]     = b;
    ((uint32_t*)ll)[j * 2 + 1] = d;
}

// Wq,Wkv -> 2-split fp16 transposed; Wo -> single fp16 transposed. One launch.
__global__ void cvtT_W(const float* __restrict__ Wq, const float* __restrict__ Wkv,
                       const float* __restrict__ Wo,
                       __half* __restrict__ wqThi, __half* __restrict__ wqTlo,
                       __half* __restrict__ wkvThi, __half* __restrict__ wkvTlo,
                       __half* __restrict__ woT)
{
    __shared__ float tile[32][33];
    int bx = blockIdx.x;
    const float* W; __half *Thi, *Tlo; int Nc, idx, do_split;
    if (bx < 256)      { W = Wq;  Thi = wqThi;  Tlo = wqTlo;  Nc = 512;  idx = bx;       do_split = 1; }
    else if (bx < 768) { W = Wkv; Thi = wkvThi; Tlo = wkvTlo; Nc = 1024; idx = bx - 256; do_split = 1; }
    else               { W = Wo;  Thi = woT;    Tlo = 0;      Nc = 512;  idx = bx - 768; do_split = 0; }
    int tn = Nc / 32;
    int n0 = (idx % tn) * 32, k0 = (idx / tn) * 32;
    for (int r = threadIdx.y; r < 32; r += 8)
        tile[r][threadIdx.x] = W[(size_t)(k0 + r) * Nc + n0 + threadIdx.x];
    __syncthreads();
    for (int r = threadIdx.y; r < 32; r += 8) {
        float x = tile[threadIdx.x][r];
        __half h = __float2half_rn(x);
        size_t o = (size_t)(n0 + r) * 512 + k0 + threadIdx.x;
        Thi[o] = h;
        if (do_split) Tlo[o] = __float2half_rn(x - __half2float(h));
    }
}

// ---------------------------------------------------------------------------
// GEMM tile: out[128x128] = (Ahi+Alo)[128x512] @ WT^T with 2 or 3 fp16 terms.
// 8 warps (2m x 4n), warp tile 64x32. All output arrays have row stride 512.
// mode 0: fp32 out; mode 1: fp16 2-split out; mode 2: fp16 single out.
// ---------------------------------------------------------------------------
__device__ __forceinline__ void gemm_body(
    const __half* __restrict__ Ahi, const __half* __restrict__ Alo,
    const __half* __restrict__ WThi, const __half* __restrict__ WTlo,
    int m0, int n0w, int n0out, int terms, int mode,
    float* __restrict__ outf, __half* __restrict__ outhi, __half* __restrict__ outlo,
    char* smem)
{
    const uint32_t sb = smem_u32(smem);
    const int t = threadIdx.x, l = t & 31, w = t >> 5;
    const int wm = w >> 2, wn = w & 3;
    const uint32_t sAh = sb, sAl = sb + GB, sWh = sb + 2 * GB, sWl = sb + 3 * GB;

    float c[4][4][4];
    #pragma unroll
    for (int i = 0; i < 4; i++)
        #pragma unroll
        for (int j = 0; j < 4; j++)
            #pragma unroll
            for (int e = 0; e < 4; e++) c[i][j][e] = 0.f;

    const int row = t >> 1, half = t & 1;
    const __half* gAh = Ahi  + (size_t)(m0 + row) * 512 + half * 32;
    const __half* gAl = Alo  + (size_t)(m0 + row) * 512 + half * 32;
    const __half* gWh = WThi + (size_t)(n0w + row) * 512 + half * 32;
    const __half* gWl = terms == 3 ? WTlo + (size_t)(n0w + row) * 512 + half * 32 : gWh;
    const uint32_t db = (uint32_t)(row * 144 + half * 64);

    for (int kb = 0; kb < 512; kb += 64) {
        #pragma unroll
        for (int v = 0; v < 4; v++) {
            cpa16(sAh + db + v * 16, gAh + kb + v * 8);
            cpa16(sAl + db + v * 16, gAl + kb + v * 8);
            cpa16(sWh + db + v * 16, gWh + kb + v * 8);
        }
        if (terms == 3) {
            #pragma unroll
            for (int v = 0; v < 4; v++)
                cpa16(sWl + db + v * 16, gWl + kb + v * 8);
        }
        CP_COMMIT();
        CP_WAIT0();
        __syncthreads();

        #pragma unroll
        for (int kk = 0; kk < 4; kk++) {
            uint32_t ah[4][4], al[4][4];
            #pragma unroll
            for (int i = 0; i < 4; i++) {
                ldsm4(ah[i], addrA(sAh, wm * 64 + i * 16, kk * 16, l));
                ldsm4(al[i], addrA(sAl, wm * 64 + i * 16, kk * 16, l));
            }
            #pragma unroll
            for (int p = 0; p < 2; p++) {
                uint32_t bh[4], bl[4];
                ldsm4(bh, addrB(sWh, wn * 32 + p * 16, kk * 16, l));
                if (terms == 3) ldsm4(bl, addrB(sWl, wn * 32 + p * 16, kk * 16, l));
                #pragma unroll
                for (int i = 0; i < 4; i++) {
                    #pragma unroll
                    for (int q = 0; q < 2; q++) {
                        float* acc = c[i][p * 2 + q];
                        mma16816(acc, ah[i], bh + q * 2);
                        mma16816(acc, al[i], bh + q * 2);
                        if (terms == 3) mma16816(acc, ah[i], bl + q * 2);
                    }
                }
            }
        }
        __syncthreads();
    }

    #pragma unroll
    for (int i = 0; i < 4; i++) {
        #pragma unroll
        for (int jn = 0; jn < 4; jn++) {
            int r0 = m0 + wm * 64 + i * 16 + (l >> 2);
            int cc = n0out + wn * 32 + jn * 8 + (l & 3) * 2;
            float* acc = c[i][jn];
            if (mode == 0) {
                *(float2*)(outf + (size_t)r0 * 512 + cc)       = make_float2(acc[0], acc[1]);
                *(float2*)(outf + (size_t)(r0 + 8) * 512 + cc) = make_float2(acc[2], acc[3]);
            } else if (mode == 1) {
                uint32_t h0, l0, h1, l1;
                split2h(acc[0], acc[1], h0, l0);
                split2h(acc[2], acc[3], h1, l1);
                *(uint32_t*)(outhi + (size_t)r0 * 512 + cc)       = h0;
                *(uint32_t*)(outlo + (size_t)r0 * 512 + cc)       = l0;
                *(uint32_t*)(outhi + (size_t)(r0 + 8) * 512 + cc) = h1;
                *(uint32_t*)(outlo + (size_t)(r0 + 8) * 512 + cc) = l1;
            } else {
                *(uint32_t*)(outhi + (size_t)r0 * 512 + cc) =
                    hpack(__float2half_rn(acc[0]), __float2half_rn(acc[1]));
                *(uint32_t*)(outhi + (size_t)(r0 + 8) * 512 + cc) =
                    hpack(__float2half_rn(acc[2]), __float2half_rn(acc[3]));
            }
        }
    }
}

// grid (12, 64): bx 0-3 Q (3-term, split out), 4-7 K (3-term, split out),
// 8-11 V (2-term, single out)
__global__ __launch_bounds__(256, 2)
void proj_qkv(const __half* __restrict__ curhi, const __half* __restrict__ curlo,
              const __half* __restrict__ hidhi, const __half* __restrict__ hidlo,
              const __half* __restrict__ wqThi, const __half* __restrict__ wqTlo,
              const __half* __restrict__ wkvThi, const __half* __restrict__ wkvTlo,
              __half* __restrict__ qhi, __half* __restrict__ qlo,
              __half* __restrict__ khi, __half* __restrict__ klo,
              __half* __restrict__ vv)
{
    extern __shared__ __align__(1024) char smem[];
    int bx = blockIdx.x, m0 = blockIdx.y * 128;
    if (bx < 4)
        gemm_body(curhi, curlo, wqThi, wqTlo, m0, bx * 128, bx * 128, 3, 1,
                  nullptr, qhi, qlo, smem);
    else if (bx < 8)
        gemm_body(hidhi, hidlo, wkvThi, wkvTlo, m0, (bx - 4) * 128, (bx - 4) * 128,
                  3, 1, nullptr, khi, klo, smem);
    else
        gemm_body(hidhi, hidlo, wkvThi, wkvTlo, m0, 512 + (bx - 8) * 128,
                  (bx - 8) * 128, 2, 2, nullptr, vv, nullptr, smem);
}

__global__ __launch_bounds__(256, 2)
void proj_out(const __half* __restrict__ aohi, const __half* __restrict__ aolo,
              const __half* __restrict__ woT, float* __restrict__ out)
{
    extern __shared__ __align__(1024) char smem[];
    gemm_body(aohi, aolo, woT, nullptr, blockIdx.y * 128, blockIdx.x * 128,
              blockIdx.x * 128, 2, 0, out, nullptr, nullptr, smem);
}

// ---------------------------------------------------------------------------
// Attention, online-max softmax (NO 1/sqrt(d) scale per reference).
// Block = (b,h) x 128 q-rows, 8 warps x 16 q-rows, TWO CTAs per SM.
// Q fragments NOT hoisted (re-ldmatrix per tile) to keep regs <= 128.
// S: 3 terms. P: fp16 2-split. PV: 2 terms.
// ---------------------------------------------------------------------------
__global__ __launch_bounds__(256, 2)
void attn_mma(const __half* __restrict__ Qhi, const __half* __restrict__ Qlo,
              const __half* __restrict__ Khi, const __half* __restrict__ Klo,
              const __half* __restrict__ Vv,
              __half* __restrict__ AOhi, __half* __restrict__ AOlo)
{
    extern __shared__ __align__(1024) char smem[];
    const uint32_t sb = smem_u32(smem);
    const uint32_t sQh = sb, sQl = sb + GB;
    const uint32_t sKh = sb + 2 * GB;
    const uint32_t sKl = sKh + 9216;
    const uint32_t sV  = sKl + 9216;

    const int t = threadIdx.x, l = t & 31, w = t >> 5;
    const int b = blockIdx.x >> 3, h = blockIdx.x & 7;
    const int q0 = blockIdx.y * 128;

    // stage resident Q tile
    {
        const int row = t >> 1, half = t & 1;
        const __half* gh = Qhi + (size_t)(b * N_ + q0 + row) * 512 + h * 64 + half * 32;
        const __half* gl = Qlo + (size_t)(b * N_ + q0 + row) * 512 + h * 64 + half * 32;
        char* dh = smem +      row * 144 + half * 64;
        char* dl = smem + GB + row * 144 + half * 64;
        #pragma unroll
        for (int v = 0; v < 4; v++) {
            ((uint4*)dh)[v] = ((const uint4*)gh)[v];
            ((uint4*)dl)[v] = ((const uint4*)gl)[v];
        }
    }
    __syncthreads();

    float o[8][4];
    #pragma unroll
    for (int i = 0; i < 8; i++)
        #pragma unroll
        for (int e = 0; e < 4; e++) o[i][e] = 0.f;
    float lsum0 = 0.f, lsum1 = 0.f;
    float m0r = -1e30f, m1r = -1e30f;

    for (int kt = 0; kt < 16; kt++) {
        // stage Khi/Klo/V tiles (3 x 64 rows x 128 B); 384 tasks over 256 thr
        for (int i = t; i < 384; i += 256) {
            int buf = i >> 7, rr = (i & 127) >> 1, hf = i & 1;
            const __half* base = (buf == 0) ? Khi : (buf == 1) ? Klo : Vv;
            const __half* src = base + (size_t)(b * N_ + kt * 64 + rr) * 512
                                + h * 64 + hf * 32;
            uint32_t d = ((buf == 0) ? sKh : (buf == 1) ? sKl : sV)
                         + (uint32_t)(rr * 144 + hf * 64);
            #pragma unroll
            for (int v = 0; v < 4; v++)
                cpa16(d + v * 16, src + v * 8);
        }
        CP_COMMIT();
        CP_WAIT0();
        __syncthreads();

        // ---- S = Q K^T (3 terms), Q frags re-loaded per tile ----
        float s[8][4];
        #pragma unroll
        for (int i = 0; i < 8; i++)
            #pragma unroll
            for (int e = 0; e < 4; e++) s[i][e] = 0.f;

        #pragma unroll
        for (int kk = 0; kk < 4; kk++) {
            uint32_t qh[4], ql[4];
            ldsm4(qh, addrA(sQh, w * 16, kk * 16, l));
            ldsm4(ql, addrA(sQl, w * 16, kk * 16, l));
            #pragma unroll
            for (int p = 0; p < 4; p++) {
                uint32_t bh[4], bl[4];
                ldsm4(bh, addrB(sKh, p * 16, kk * 16, l));
                ldsm4(bl, addrB(sKl, p * 16, kk * 16, l));
                #pragma unroll
                for (int q = 0; q < 2; q++) {
                    float* acc = s[p * 2 + q];
                    mma16816(acc, qh, bh + q * 2);
                    mma16816(acc, ql, bh + q * 2);
                    mma16816(acc, qh, bl + q * 2);
                }
            }
        }

        // ---- online max over this tile's rows ----
        float rm0 = -1e30f, rm1 = -1e30f;
        #pragma unroll
        for (int jn = 0; jn < 8; jn++) {
            rm0 = fmaxf(rm0, fmaxf(s[jn][0], s[jn][1]));
            rm1 = fmaxf(rm1, fmaxf(s[jn][2], s[jn][3]));
        }
        rm0 = fmaxf(rm0, __shfl_xor_sync(0xffffffffu, rm0, 1));
        rm0 = fmaxf(rm0, __shfl_xor_sync(0xffffffffu, rm0, 2));
        rm1 = fmaxf(rm1, __shfl_xor_sync(0xffffffffu, rm1, 1));
        rm1 = fmaxf(rm1, __shfl_xor_sync(0xffffffffu, rm1, 2));
        float m0n = fmaxf(m0r, rm0), m1n = fmaxf(m1r, rm1);
        float sc0 = __expf(m0r - m0n), sc1 = __expf(m1r - m1n);
        m0r = m0n; m1r = m1n;
        lsum0 *= sc0; lsum1 *= sc1;
        #pragma unroll
        for (int i = 0; i < 8; i++) {
            o[i][0] *= sc0; o[i][1] *= sc0;
            o[i][2] *= sc1; o[i][3] *= sc1;
        }

        // ---- exp + row sums + pack P (fp16 2-split, values in [0,1]) ----
        uint32_t pa_h[4][4], pa_l[4][4];
        #pragma unroll
        for (int jn = 0; jn < 8; jn++) {
            float e0 = __expf(s[jn][0] - m0r);
            float e1 = __expf(s[jn][1] - m0r);
            float e2 = __expf(s[jn][2] - m1r);
            float e3 = __expf(s[jn][3] - m1r);
            lsum0 += e0 + e1;
            lsum1 += e2 + e3;
            int kj = jn >> 1, base = (jn & 1) * 2;
            split2h(e0, e1, pa_h[kj][base + 0], pa_l[kj][base + 0]);
            split2h(e2, e3, pa_h[kj][base + 1], pa_l[kj][base + 1]);
        }

        // ---- O += P V (2 terms) ----
        #pragma unroll
        for (int kj = 0; kj < 4; kj++) {
            #pragma unroll
            for (int pd = 0; pd < 4; pd++) {
                uint32_t bv[4];
                uint32_t va = (uint32_t)((kj * 16 + ((l >> 3) & 1) * 8 + (l & 7)) * 144
                                         + (pd * 16 + ((l >> 4) & 1) * 8) * 2);
                ldsm4t(bv, sV + va);
                #pragma unroll
                for (int q = 0; q < 2; q++) {
                    float* acc = o[pd * 2 + q];
                    mma16816(acc, pa_h[kj], bv + q * 2);
                    mma16816(acc, pa_l[kj], bv + q * 2);
                }
            }
        }
        __syncthreads();
    }

    lsum0 += __shfl_xor_sync(0xffffffffu, lsum0, 1);
    lsum0 += __shfl_xor_sync(0xffffffffu, lsum0, 2);
    lsum1 += __shfl_xor_sync(0xffffffffu, lsum1, 1);
    lsum1 += __shfl_xor_sync(0xffffffffu, lsum1, 2);
    float inv0 = 1.f / lsum0, inv1 = 1.f / lsum1;

    const int rowg = b * N_ + q0 + w * 16 + (l >> 2);
    #pragma unroll
    for (int dn = 0; dn < 8; dn++) {
        int cc = h * 64 + dn * 8 + (l & 3) * 2;
        uint32_t h0, l0, h1, l1;
        split2h(o[dn][0] * inv0, o[dn][1] * inv0, h0, l0);
        split2h(o[dn][2] * inv1, o[dn][3] * inv1, h1, l1);
        *(uint32_t*)(AOhi + (size_t)rowg * 512 + cc)       = h0;
        *(uint32_t*)(AOlo + (size_t)rowg * 512 + cc)       = l0;
        *(uint32_t*)(AOhi + (size_t)(rowg + 8) * 512 + cc) = h1;
        *(uint32_t*)(AOlo + (size_t)(rowg + 8) * 512 + cc) = l1;
    }
}

// ---------------------------------------------------------------------------
extern "C" void kernel_launch(void* const* d_in, const int* in_sizes, int n_in,
                              void* d_out, int out_size)
{
    (void)in_sizes; (void)n_in; (void)out_size;
    const float* current = (const float*)d_in[0];
    const float* hidden  = (const float*)d_in[1];
    const float* Wq      = (const float*)d_in[2];
    const float* Wkv     = (const float*)d_in[3];
    const float* Wo      = (const float*)d_in[4];
    float* out           = (float*)d_out;

    __half *curhi, *curlo, *hidhi, *hidlo;
    __half *wqThi, *wqTlo, *wkvThi, *wkvTlo, *woT;
    __half *qhi, *qlo, *khi, *klo, *vv, *aohi, *aolo;
    cudaGetSymbolAddress((void**)&curhi, g_curhi); cudaGetSymbolAddress((void**)&curlo, g_curlo);
    cudaGetSymbolAddress((void**)&hidhi, g_hidhi); cudaGetSymbolAddress((void**)&hidlo, g_hidlo);
    cudaGetSymbolAddress((void**)&wqThi, g_wqThi); cudaGetSymbolAddress((void**)&wqTlo, g_wqTlo);
    cudaGetSymbolAddress((void**)&wkvThi, g_wkvThi); cudaGetSymbolAddress((void**)&wkvTlo, g_wkvTlo);
    cudaGetSymbolAddress((void**)&woT, g_woT);
    cudaGetSymbolAddress((void**)&qhi, g_qhi);   cudaGetSymbolAddress((void**)&qlo, g_qlo);
    cudaGetSymbolAddress((void**)&khi, g_khi);   cudaGetSymbolAddress((void**)&klo, g_klo);
    cudaGetSymbolAddress((void**)&vv,  g_v);
    cudaGetSymbolAddress((void**)&aohi, g_aohi); cudaGetSymbolAddress((void**)&aolo, g_aolo);

    const int gemm_smem = 4 * GB;                    // 73728
    const int attn_smem = 2 * GB + 3 * 9216;         // 64512
    cudaFuncSetAttribute(proj_qkv, cudaFuncAttributeMaxDynamicSharedMemorySize, gemm_smem);
    cudaFuncSetAttribute(proj_out, cudaFuncAttributeMaxDynamicSharedMemorySize, gemm_smem);
    cudaFuncSetAttribute(attn_mma, cudaFuncAttributeMaxDynamicSharedMemorySize, attn_smem);

    const int n4 = MT_ * DM_ / 4;
    split_two<<<2 * n4 / 256, 256>>>(current, hidden, curhi, curlo, hidhi, hidlo, n4);
    cvtT_W<<<1024, dim3(32, 8)>>>(Wq, Wkv, Wo, wqThi, wqTlo, wkvThi, wkvTlo, woT);

    proj_qkv<<<dim3(12, 64), 256, gemm_smem>>>(curhi, curlo, hidhi, hidlo,
                                               wqThi, wqTlo, wkvThi, wkvTlo,
                                               qhi, qlo, khi, klo, vv);
    attn_mma<<<dim3(B_ * H_, N_ / 128), 256, attn_smem>>>(qhi, qlo, khi, klo, vv,
                                                          aohi, aolo);
    proj_out<<<dim3(4, 64), 256, gemm_smem>>>(aohi, aolo, woT, out);
}

// round 10
// speedup vs baseline: 1.3847x; 1.0544x over previous
#include <cuda_runtime.h>
#include <cuda_fp16.h>
#include <cstdint>
#include <math.h>

#define B_   8
#define N_   1024
#define DM_  512
#define H_   8
#define MT_  (B_ * N_)      // 8192
#define GB   18432          // 128 rows x 144 B smem buffer

// ---------------- fp16 scratch (__device__ globals; no allocs) -------------
__device__ __half g_curhi[MT_ * DM_], g_curlo[MT_ * DM_];
__device__ __half g_hidhi[MT_ * DM_], g_hidlo[MT_ * DM_];
__device__ __half g_wqThi [DM_ * DM_],     g_wqTlo [DM_ * DM_];
__device__ __half g_wkvThi[2 * DM_ * DM_], g_wkvTlo[2 * DM_ * DM_];
__device__ __half g_woT   [DM_ * DM_];
__device__ __half g_qhi[MT_ * DM_], g_qlo[MT_ * DM_];
__device__ __half g_khi[MT_ * DM_], g_klo[MT_ * DM_];
__device__ __half g_v  [MT_ * DM_];
__device__ __half g_aohi[MT_ * DM_], g_aolo[MT_ * DM_];

// ---------------- helpers ---------------------------------------------------
__device__ __forceinline__ uint32_t smem_u32(const void* p) {
    uint32_t a;
    asm("{ .reg .u64 t; cvta.to.shared.u64 t, %1; cvt.u32.u64 %0, t; }" : "=r"(a) : "l"(p));
    return a;
}
__device__ __forceinline__ void cpa16(uint32_t dst, const void* src) {
    asm volatile("cp.async.cg.shared.global [%0], [%1], 16;" :: "r"(dst), "l"(src));
}
#define CP_COMMIT() asm volatile("cp.async.commit_group;" ::: "memory")
#define CP_WAIT0()  asm volatile("cp.async.wait_group 0;" ::: "memory")

__device__ __forceinline__ void ldsm4(uint32_t* r, uint32_t addr) {
    asm volatile("ldmatrix.sync.aligned.m8n8.x4.shared.b16 {%0,%1,%2,%3}, [%4];"
        : "=r"(r[0]), "=r"(r[1]), "=r"(r[2]), "=r"(r[3]) : "r"(addr));
}
__device__ __forceinline__ void ldsm4t(uint32_t* r, uint32_t addr) {
    asm volatile("ldmatrix.sync.aligned.m8n8.x4.trans.shared.b16 {%0,%1,%2,%3}, [%4];"
        : "=r"(r[0]), "=r"(r[1]), "=r"(r[2]), "=r"(r[3]) : "r"(addr));
}
__device__ __forceinline__ void mma16816(float* c, const uint32_t* a, const uint32_t* b) {
    asm volatile("mma.sync.aligned.m16n8k16.row.col.f32.f16.f16.f32 "
        "{%0,%1,%2,%3}, {%4,%5,%6,%7}, {%8,%9}, {%0,%1,%2,%3};"
        : "+f"(c[0]), "+f"(c[1]), "+f"(c[2]), "+f"(c[3])
        : "r"(a[0]), "r"(a[1]), "r"(a[2]), "r"(a[3]), "r"(b[0]), "r"(b[1]));
}
__device__ __forceinline__ uint32_t hpack(__half a, __half b) {
    __half2 t; t.x = a; t.y = b;
    return *(uint32_t*)&t;
}
__device__ __forceinline__ uint32_t pack2h(float v0, float v1) {
    return hpack(__float2half_rn(v0), __float2half_rn(v1));
}
__device__ __forceinline__ void split2h(float v0, float v1, uint32_t& hi, uint32_t& lo) {
    __half h0 = __float2half_rn(v0), h1 = __float2half_rn(v1);
    __half l0 = __float2half_rn(v0 - __half2float(h0));
    __half l1 = __float2half_rn(v1 - __half2float(h1));
    hi = hpack(h0, h1); lo = hpack(l0, l1);
}

// smem rows 144 B (72 halves) -> conflict-free ldmatrix
__device__ __forceinline__ uint32_t addrA(uint32_t base, int row, int col, int l) {
    return base + (uint32_t)((row + (l & 15)) * 144 + (col + (l >> 4) * 8) * 2);
}
__device__ __forceinline__ uint32_t addrB(uint32_t base, int row, int col, int l) {
    return base + (uint32_t)((row + ((l >> 4) & 1) * 8 + (l & 7)) * 144
                             + (col + ((l >> 3) & 1) * 8) * 2);
}

// ---------------------------------------------------------------------------
// conversions
// ---------------------------------------------------------------------------
__global__ void split_two(const float* __restrict__ x0, const float* __restrict__ x1,
                          __half* __restrict__ h0, __half* __restrict__ l0p,
                          __half* __restrict__ h1, __half* __restrict__ l1p, int n4)
{
    int i = blockIdx.x * blockDim.x + threadIdx.x;
    const float* x = (i < n4) ? x0 : x1;
    __half* hh = (i < n4) ? h0 : h1;
    __half* ll = (i < n4) ? l0p : l1p;
    int j = (i < n4) ? i : i - n4;
    float4 v = ((const float4*)x)[j];
    uint32_t a, b, c, d;
    split2h(v.x, v.y, a, b);
    split2h(v.z, v.w, c, d);
    ((uint32_t*)hh)[j * 2]     = a;
    ((uint32_t*)hh)[j * 2 + 1] = c;
    ((uint32_t*)ll)[j * 2]     = b;
    ((uint32_t*)ll)[j * 2 + 1] = d;
}

// Wq,Wkv -> 2-split fp16 transposed; Wo -> single fp16 transposed. One launch.
__global__ void cvtT_W(const float* __restrict__ Wq, const float* __restrict__ Wkv,
                       const float* __restrict__ Wo,
                       __half* __restrict__ wqThi, __half* __restrict__ wqTlo,
                       __half* __restrict__ wkvThi, __half* __restrict__ wkvTlo,
                       __half* __restrict__ woT)
{
    __shared__ float tile[32][33];
    int bx = blockIdx.x;
    const float* W; __half *Thi, *Tlo; int Nc, idx, do_split;
    if (bx < 256)      { W = Wq;  Thi = wqThi;  Tlo = wqTlo;  Nc = 512;  idx = bx;       do_split = 1; }
    else if (bx < 768) { W = Wkv; Thi = wkvThi; Tlo = wkvTlo; Nc = 1024; idx = bx - 256; do_split = 1; }
    else               { W = Wo;  Thi = woT;    Tlo = 0;      Nc = 512;  idx = bx - 768; do_split = 0; }
    int tn = Nc / 32;
    int n0 = (idx % tn) * 32, k0 = (idx / tn) * 32;
    for (int r = threadIdx.y; r < 32; r += 8)
        tile[r][threadIdx.x] = W[(size_t)(k0 + r) * Nc + n0 + threadIdx.x];
    __syncthreads();
    for (int r = threadIdx.y; r < 32; r += 8) {
        float x = tile[threadIdx.x][r];
        __half h = __float2half_rn(x);
        size_t o = (size_t)(n0 + r) * 512 + k0 + threadIdx.x;
        Thi[o] = h;
        if (do_split) Tlo[o] = __float2half_rn(x - __half2float(h));
    }
}

// ---------------------------------------------------------------------------
// GEMM tile: out[128x128] = (Ahi+Alo)[128x512] @ WT^T with 2 or 3 fp16 terms.
// 8 warps (2m x 4n), warp tile 64x32. All output arrays have row stride 512.
// mode 0: fp32 out; mode 1: fp16 2-split out; mode 2: fp16 single out.
// ---------------------------------------------------------------------------
__device__ __forceinline__ void gemm_body(
    const __half* __restrict__ Ahi, const __half* __restrict__ Alo,
    const __half* __restrict__ WThi, const __half* __restrict__ WTlo,
    int m0, int n0w, int n0out, int terms, int mode,
    float* __restrict__ outf, __half* __restrict__ outhi, __half* __restrict__ outlo,
    char* smem)
{
    const uint32_t sb = smem_u32(smem);
    const int t = threadIdx.x, l = t & 31, w = t >> 5;
    const int wm = w >> 2, wn = w & 3;
    const uint32_t sAh = sb, sAl = sb + GB, sWh = sb + 2 * GB, sWl = sb + 3 * GB;

    float c[4][4][4];
    #pragma unroll
    for (int i = 0; i < 4; i++)
        #pragma unroll
        for (int j = 0; j < 4; j++)
            #pragma unroll
            for (int e = 0; e < 4; e++) c[i][j][e] = 0.f;

    const int row = t >> 1, half = t & 1;
    const __half* gAh = Ahi  + (size_t)(m0 + row) * 512 + half * 32;
    const __half* gAl = Alo  + (size_t)(m0 + row) * 512 + half * 32;
    const __half* gWh = WThi + (size_t)(n0w + row) * 512 + half * 32;
    const __half* gWl = terms == 3 ? WTlo + (size_t)(n0w + row) * 512 + half * 32 : gWh;
    const uint32_t db = (uint32_t)(row * 144 + half * 64);

    for (int kb = 0; kb < 512; kb += 64) {
        #pragma unroll
        for (int v = 0; v < 4; v++) {
            cpa16(sAh + db + v * 16, gAh + kb + v * 8);
            cpa16(sAl + db + v * 16, gAl + kb + v * 8);
            cpa16(sWh + db + v * 16, gWh + kb + v * 8);
        }
        if (terms == 3) {
            #pragma unroll
            for (int v = 0; v < 4; v++)
                cpa16(sWl + db + v * 16, gWl + kb + v * 8);
        }
        CP_COMMIT();
        CP_WAIT0();
        __syncthreads();

        #pragma unroll
        for (int kk = 0; kk < 4; kk++) {
            uint32_t ah[4][4], al[4][4];
            #pragma unroll
            for (int i = 0; i < 4; i++) {
                ldsm4(ah[i], addrA(sAh, wm * 64 + i * 16, kk * 16, l));
                ldsm4(al[i], addrA(sAl, wm * 64 + i * 16, kk * 16, l));
            }
            #pragma unroll
            for (int p = 0; p < 2; p++) {
                uint32_t bh[4], bl[4];
                ldsm4(bh, addrB(sWh, wn * 32 + p * 16, kk * 16, l));
                if (terms == 3) ldsm4(bl, addrB(sWl, wn * 32 + p * 16, kk * 16, l));
                #pragma unroll
                for (int i = 0; i < 4; i++) {
                    #pragma unroll
                    for (int q = 0; q < 2; q++) {
                        float* acc = c[i][p * 2 + q];
                        mma16816(acc, ah[i], bh + q * 2);
                        mma16816(acc, al[i], bh + q * 2);
                        if (terms == 3) mma16816(acc, ah[i], bl + q * 2);
                    }
                }
            }
        }
        __syncthreads();
    }

    #pragma unroll
    for (int i = 0; i < 4; i++) {
        #pragma unroll
        for (int jn = 0; jn < 4; jn++) {
            int r0 = m0 + wm * 64 + i * 16 + (l >> 2);
            int cc = n0out + wn * 32 + jn * 8 + (l & 3) * 2;
            float* acc = c[i][jn];
            if (mode == 0) {
                *(float2*)(outf + (size_t)r0 * 512 + cc)       = make_float2(acc[0], acc[1]);
                *(float2*)(outf + (size_t)(r0 + 8) * 512 + cc) = make_float2(acc[2], acc[3]);
            } else if (mode == 1) {
                uint32_t h0, l0, h1, l1;
                split2h(acc[0], acc[1], h0, l0);
                split2h(acc[2], acc[3], h1, l1);
                *(uint32_t*)(outhi + (size_t)r0 * 512 + cc)       = h0;
                *(uint32_t*)(outlo + (size_t)r0 * 512 + cc)       = l0;
                *(uint32_t*)(outhi + (size_t)(r0 + 8) * 512 + cc) = h1;
                *(uint32_t*)(outlo + (size_t)(r0 + 8) * 512 + cc) = l1;
            } else {
                *(uint32_t*)(outhi + (size_t)r0 * 512 + cc)       = pack2h(acc[0], acc[1]);
                *(uint32_t*)(outhi + (size_t)(r0 + 8) * 512 + cc) = pack2h(acc[2], acc[3]);
            }
        }
    }
}

// grid (12, 64): bx 0-3 Q (3-term, split out), 4-7 K (3-term, split out),
// 8-11 V (2-term, single out)
__global__ __launch_bounds__(256, 2)
void proj_qkv(const __half* __restrict__ curhi, const __half* __restrict__ curlo,
              const __half* __restrict__ hidhi, const __half* __restrict__ hidlo,
              const __half* __restrict__ wqThi, const __half* __restrict__ wqTlo,
              const __half* __restrict__ wkvThi, const __half* __restrict__ wkvTlo,
              __half* __restrict__ qhi, __half* __restrict__ qlo,
              __half* __restrict__ khi, __half* __restrict__ klo,
              __half* __restrict__ vv)
{
    extern __shared__ __align__(1024) char smem[];
    int bx = blockIdx.x, m0 = blockIdx.y * 128;
    if (bx < 4)
        gemm_body(curhi, curlo, wqThi, wqTlo, m0, bx * 128, bx * 128, 3, 1,
                  nullptr, qhi, qlo, smem);
    else if (bx < 8)
        gemm_body(hidhi, hidlo, wkvThi, wkvTlo, m0, (bx - 4) * 128, (bx - 4) * 128,
                  3, 1, nullptr, khi, klo, smem);
    else
        gemm_body(hidhi, hidlo, wkvThi, wkvTlo, m0, 512 + (bx - 8) * 128,
                  (bx - 8) * 128, 2, 2, nullptr, vv, nullptr, smem);
}

__global__ __launch_bounds__(256, 2)
void proj_out(const __half* __restrict__ aohi, const __half* __restrict__ aolo,
              const __half* __restrict__ woT, float* __restrict__ out)
{
    extern __shared__ __align__(1024) char smem[];
    gemm_body(aohi, aolo, woT, nullptr, blockIdx.y * 128, blockIdx.x * 128,
              blockIdx.x * 128, 2, 0, out, nullptr, nullptr, smem);
}

// ---------------------------------------------------------------------------
// Attention, online-max softmax with lazy rescale (NO 1/sqrt(d) scale).
// Block = (b,h) x 128 q-rows, 8 warps x 16 q-rows, two CTAs per SM.
// S: Q 2-split x K 2-split, 3 terms.  P: SINGLE fp16 (P in [0,1], rn error
// <= 2^-12 relative -> ~1.4e-4 on O).  PV: 1 term.
// ---------------------------------------------------------------------------
__global__ __launch_bounds__(256, 2)
void attn_mma(const __half* __restrict__ Qhi, const __half* __restrict__ Qlo,
              const __half* __restrict__ Khi, const __half* __restrict__ Klo,
              const __half* __restrict__ Vv,
              __half* __restrict__ AOhi, __half* __restrict__ AOlo)
{
    extern __shared__ __align__(1024) char smem[];
    const uint32_t sb = smem_u32(smem);
    const uint32_t sQh = sb, sQl = sb + GB;
    const uint32_t sKh = sb + 2 * GB;
    const uint32_t sKl = sKh + 9216;
    const uint32_t sV  = sKl + 9216;

    const int t = threadIdx.x, l = t & 31, w = t >> 5;
    const int b = blockIdx.x >> 3, h = blockIdx.x & 7;
    const int q0 = blockIdx.y * 128;

    // stage resident Q tile
    {
        const int row = t >> 1, half = t & 1;
        const __half* gh = Qhi + (size_t)(b * N_ + q0 + row) * 512 + h * 64 + half * 32;
        const __half* gl = Qlo + (size_t)(b * N_ + q0 + row) * 512 + h * 64 + half * 32;
        char* dh = smem +      row * 144 + half * 64;
        char* dl = smem + GB + row * 144 + half * 64;
        #pragma unroll
        for (int v = 0; v < 4; v++) {
            ((uint4*)dh)[v] = ((const uint4*)gh)[v];
            ((uint4*)dl)[v] = ((const uint4*)gl)[v];
        }
    }
    __syncthreads();

    float o[8][4];
    #pragma unroll
    for (int i = 0; i < 8; i++)
        #pragma unroll
        for (int e = 0; e < 4; e++) o[i][e] = 0.f;
    float lsum0 = 0.f, lsum1 = 0.f;
    float m0r = -1e30f, m1r = -1e30f;

    for (int kt = 0; kt < 16; kt++) {
        // stage Khi/Klo/V tiles (3 x 64 rows x 128 B); 384 tasks over 256 thr
        for (int i = t; i < 384; i += 256) {
            int buf = i >> 7, rr = (i & 127) >> 1, hf = i & 1;
            const __half* base = (buf == 0) ? Khi : (buf == 1) ? Klo : Vv;
            const __half* src = base + (size_t)(b * N_ + kt * 64 + rr) * 512
                                + h * 64 + hf * 32;
            uint32_t d = ((buf == 0) ? sKh : (buf == 1) ? sKl : sV)
                         + (uint32_t)(rr * 144 + hf * 64);
            #pragma unroll
            for (int v = 0; v < 4; v++)
                cpa16(d + v * 16, src + v * 8);
        }
        CP_COMMIT();
        CP_WAIT0();
        __syncthreads();

        // ---- S = Q K^T (3 terms), Q frags re-loaded per tile ----
        float s[8][4];
        #pragma unroll
        for (int i = 0; i < 8; i++)
            #pragma unroll
            for (int e = 0; e < 4; e++) s[i][e] = 0.f;

        #pragma unroll
        for (int kk = 0; kk < 4; kk++) {
            uint32_t qh[4], ql[4];
            ldsm4(qh, addrA(sQh, w * 16, kk * 16, l));
            ldsm4(ql, addrA(sQl, w * 16, kk * 16, l));
            #pragma unroll
            for (int p = 0; p < 4; p++) {
                uint32_t bh[4], bl[4];
                ldsm4(bh, addrB(sKh, p * 16, kk * 16, l));
                ldsm4(bl, addrB(sKl, p * 16, kk * 16, l));
                #pragma unroll
                for (int q = 0; q < 2; q++) {
                    float* acc = s[p * 2 + q];
                    mma16816(acc, qh, bh + q * 2);
                    mma16816(acc, ql, bh + q * 2);
                    mma16816(acc, qh, bl + q * 2);
                }
            }
        }

        // ---- online max; rescale only if max advanced (warp-uniform) ----
        float rm0 = -1e30f, rm1 = -1e30f;
        #pragma unroll
        for (int jn = 0; jn < 8; jn++) {
            rm0 = fmaxf(rm0, fmaxf(s[jn][0], s[jn][1]));
            rm1 = fmaxf(rm1, fmaxf(s[jn][2], s[jn][3]));
        }
        rm0 = fmaxf(rm0, __shfl_xor_sync(0xffffffffu, rm0, 1));
        rm0 = fmaxf(rm0, __shfl_xor_sync(0xffffffffu, rm0, 2));
        rm1 = fmaxf(rm1, __shfl_xor_sync(0xffffffffu, rm1, 1));
        rm1 = fmaxf(rm1, __shfl_xor_sync(0xffffffffu, rm1, 2));
        if (rm0 > m0r) {
            float sc0 = __expf(m0r - rm0);
            m0r = rm0;
            lsum0 *= sc0;
            #pragma unroll
            for (int i = 0; i < 8; i++) { o[i][0] *= sc0; o[i][1] *= sc0; }
        }
        if (rm1 > m1r) {
            float sc1 = __expf(m1r - rm1);
            m1r = rm1;
            lsum1 *= sc1;
            #pragma unroll
            for (int i = 0; i < 8; i++) { o[i][2] *= sc1; o[i][3] *= sc1; }
        }

        // ---- exp + row sums + pack P (single fp16; P in [0,1]) ----
        uint32_t pa[4][4];
        #pragma unroll
        for (int jn = 0; jn < 8; jn++) {
            float e0 = __expf(s[jn][0] - m0r);
            float e1 = __expf(s[jn][1] - m0r);
            float e2 = __expf(s[jn][2] - m1r);
            float e3 = __expf(s[jn][3] - m1r);
            lsum0 += e0 + e1;
            lsum1 += e2 + e3;
            int kj = jn >> 1, base = (jn & 1) * 2;
            pa[kj][base + 0] = pack2h(e0, e1);
            pa[kj][base + 1] = pack2h(e2, e3);
        }

        // ---- O += P V (1 term) ----
        #pragma unroll
        for (int kj = 0; kj < 4; kj++) {
            #pragma unroll
            for (int pd = 0; pd < 4; pd++) {
                uint32_t bv[4];
                uint32_t va = (uint32_t)((kj * 16 + ((l >> 3) & 1) * 8 + (l & 7)) * 144
                                         + (pd * 16 + ((l >> 4) & 1) * 8) * 2);
                ldsm4t(bv, sV + va);
                #pragma unroll
                for (int q = 0; q < 2; q++)
                    mma16816(o[pd * 2 + q], pa[kj], bv + q * 2);
            }
        }
        __syncthreads();
    }

    lsum0 += __shfl_xor_sync(0xffffffffu, lsum0, 1);
    lsum0 += __shfl_xor_sync(0xffffffffu, lsum0, 2);
    lsum1 += __shfl_xor_sync(0xffffffffu, lsum1, 1);
    lsum1 += __shfl_xor_sync(0xffffffffu, lsum1, 2);
    float inv0 = 1.f / lsum0, inv1 = 1.f / lsum1;

    const int rowg = b * N_ + q0 + w * 16 + (l >> 2);
    #pragma unroll
    for (int dn = 0; dn < 8; dn++) {
        int cc = h * 64 + dn * 8 + (l & 3) * 2;
        uint32_t h0, l0, h1, l1;
        split2h(o[dn][0] * inv0, o[dn][1] * inv0, h0, l0);
        split2h(o[dn][2] * inv1, o[dn][3] * inv1, h1, l1);
        *(uint32_t*)(AOhi + (size_t)rowg * 512 + cc)       = h0;
        *(uint32_t*)(AOlo + (size_t)rowg * 512 + cc)       = l0;
        *(uint32_t*)(AOhi + (size_t)(rowg + 8) * 512 + cc) = h1;
        *(uint32_t*)(AOlo + (size_t)(rowg + 8) * 512 + cc) = l1;
    }
}

// ---------------------------------------------------------------------------
extern "C" void kernel_launch(void* const* d_in, const int* in_sizes, int n_in,
                              void* d_out, int out_size)
{
    (void)in_sizes; (void)n_in; (void)out_size;
    const float* current = (const float*)d_in[0];
    const float* hidden  = (const float*)d_in[1];
    const float* Wq      = (const float*)d_in[2];
    const float* Wkv     = (const float*)d_in[3];
    const float* Wo      = (const float*)d_in[4];
    float* out           = (float*)d_out;

    __half *curhi, *curlo, *hidhi, *hidlo;
    __half *wqThi, *wqTlo, *wkvThi, *wkvTlo, *woT;
    __half *qhi, *qlo, *khi, *klo, *vv, *aohi, *aolo;
    cudaGetSymbolAddress((void**)&curhi, g_curhi); cudaGetSymbolAddress((void**)&curlo, g_curlo);
    cudaGetSymbolAddress((void**)&hidhi, g_hidhi); cudaGetSymbolAddress((void**)&hidlo, g_hidlo);
    cudaGetSymbolAddress((void**)&wqThi, g_wqThi); cudaGetSymbolAddress((void**)&wqTlo, g_wqTlo);
    cudaGetSymbolAddress((void**)&wkvThi, g_wkvThi); cudaGetSymbolAddress((void**)&wkvTlo, g_wkvTlo);
    cudaGetSymbolAddress((void**)&woT, g_woT);
    cudaGetSymbolAddress((void**)&qhi, g_qhi);   cudaGetSymbolAddress((void**)&qlo, g_qlo);
    cudaGetSymbolAddress((void**)&khi, g_khi);   cudaGetSymbolAddress((void**)&klo, g_klo);
    cudaGetSymbolAddress((void**)&vv,  g_v);
    cudaGetSymbolAddress((void**)&aohi, g_aohi); cudaGetSymbolAddress((void**)&aolo, g_aolo);

    const int gemm_smem = 4 * GB;                    // 73728
    const int attn_smem = 2 * GB + 3 * 9216;         // 64512
    cudaFuncSetAttribute(proj_qkv, cudaFuncAttributeMaxDynamicSharedMemorySize, gemm_smem);
    cudaFuncSetAttribute(proj_out, cudaFuncAttributeMaxDynamicSharedMemorySize, gemm_smem);
    cudaFuncSetAttribute(attn_mma, cudaFuncAttributeMaxDynamicSharedMemorySize, attn_smem);

    const int n4 = MT_ * DM_ / 4;
    split_two<<<2 * n4 / 256, 256>>>(current, hidden, curhi, curlo, hidhi, hidlo, n4);
    cvtT_W<<<1024, dim3(32, 8)>>>(Wq, Wkv, Wo, wqThi, wqTlo, wkvThi, wkvTlo, woT);

    proj_qkv<<<dim3(12, 64), 256, gemm_smem>>>(curhi, curlo, hidhi, hidlo,
                                               wqThi, wqTlo, wkvThi, wkvTlo,
                                               qhi, qlo, khi, klo, vv);
    attn_mma<<<dim3(B_ * H_, N_ / 128), 256, attn_smem>>>(qhi, qlo, khi, klo, vv,
                                                          aohi, aolo);
    proj_out<<<dim3(4, 64), 256, gemm_smem>>>(aohi, aolo, woT, out);
}

// round 11
// speedup vs baseline: 1.5393x; 1.1117x over previous
#include <cuda_runtime.h>
#include <cuda_fp16.h>
#include <cstdint>
#include <math.h>

#define B_   8
#define N_   1024
#define DM_  512
#define H_   8
#define MT_  (B_ * N_)      // 8192
#define GB   18432          // 128 rows x 144 B (Q tiles in attention)

// GEMM pipeline geometry: BK=32, rows of 80 B, 4 buffers, 2 stages
#define GROW 80
#define GBUF 10240          // 128 * 80
#define GSTG 40960          // 4 * GBUF
// Attention KV stage: 3 buffers x (64 rows x 144 B)
#define KVB  9216
#define KVSTG (3 * KVB)     // 27648

// ---------------- fp16 scratch (__device__ globals; no allocs) -------------
__device__ __half g_curhi[MT_ * DM_], g_curlo[MT_ * DM_];
__device__ __half g_hidhi[MT_ * DM_], g_hidlo[MT_ * DM_];
__device__ __half g_wqThi [DM_ * DM_],     g_wqTlo [DM_ * DM_];
__device__ __half g_wkvThi[2 * DM_ * DM_], g_wkvTlo[2 * DM_ * DM_];
__device__ __half g_woT   [DM_ * DM_];
__device__ __half g_qhi[MT_ * DM_], g_qlo[MT_ * DM_];
__device__ __half g_khi[MT_ * DM_], g_klo[MT_ * DM_];
__device__ __half g_v  [MT_ * DM_];
__device__ __half g_aohi[MT_ * DM_], g_aolo[MT_ * DM_];

// ---------------- helpers ---------------------------------------------------
__device__ __forceinline__ uint32_t smem_u32(const void* p) {
    uint32_t a;
    asm("{ .reg .u64 t; cvta.to.shared.u64 t, %1; cvt.u32.u64 %0, t; }" : "=r"(a) : "l"(p));
    return a;
}
__device__ __forceinline__ void cpa16(uint32_t dst, const void* src) {
    asm volatile("cp.async.cg.shared.global [%0], [%1], 16;" :: "r"(dst), "l"(src));
}
#define CP_COMMIT() asm volatile("cp.async.commit_group;" ::: "memory")
#define CP_WAIT0()  asm volatile("cp.async.wait_group 0;" ::: "memory")

__device__ __forceinline__ void ldsm4(uint32_t* r, uint32_t addr) {
    asm volatile("ldmatrix.sync.aligned.m8n8.x4.shared.b16 {%0,%1,%2,%3}, [%4];"
        : "=r"(r[0]), "=r"(r[1]), "=r"(r[2]), "=r"(r[3]) : "r"(addr));
}
__device__ __forceinline__ void ldsm4t(uint32_t* r, uint32_t addr) {
    asm volatile("ldmatrix.sync.aligned.m8n8.x4.trans.shared.b16 {%0,%1,%2,%3}, [%4];"
        : "=r"(r[0]), "=r"(r[1]), "=r"(r[2]), "=r"(r[3]) : "r"(addr));
}
__device__ __forceinline__ void mma16816(float* c, const uint32_t* a, const uint32_t* b) {
    asm volatile("mma.sync.aligned.m16n8k16.row.col.f32.f16.f16.f32 "
        "{%0,%1,%2,%3}, {%4,%5,%6,%7}, {%8,%9}, {%0,%1,%2,%3};"
        : "+f"(c[0]), "+f"(c[1]), "+f"(c[2]), "+f"(c[3])
        : "r"(a[0]), "r"(a[1]), "r"(a[2]), "r"(a[3]), "r"(b[0]), "r"(b[1]));
}
__device__ __forceinline__ uint32_t hpack(__half a, __half b) {
    __half2 t; t.x = a; t.y = b;
    return *(uint32_t*)&t;
}
__device__ __forceinline__ uint32_t pack2h(float v0, float v1) {
    return hpack(__float2half_rn(v0), __float2half_rn(v1));
}
__device__ __forceinline__ void split2h(float v0, float v1, uint32_t& hi, uint32_t& lo) {
    __half h0 = __float2half_rn(v0), h1 = __float2half_rn(v1);
    __half l0 = __float2half_rn(v0 - __half2float(h0));
    __half l1 = __float2half_rn(v1 - __half2float(h1));
    hi = hpack(h0, h1); lo = hpack(l0, l1);
}

// 144-B-stride tiles (attention Q / KV) -> conflict-free ldmatrix
__device__ __forceinline__ uint32_t addrA(uint32_t base, int row, int col, int l) {
    return base + (uint32_t)((row + (l & 15)) * 144 + (col + (l >> 4) * 8) * 2);
}
__device__ __forceinline__ uint32_t addrB(uint32_t base, int row, int col, int l) {
    return base + (uint32_t)((row + ((l >> 4) & 1) * 8 + (l & 7)) * 144
                             + (col + ((l >> 3) & 1) * 8) * 2);
}
// 80-B-stride tiles (GEMM, BK=32); banks (20*i mod 32) cover all 32 -> conflict-free
__device__ __forceinline__ uint32_t addrA80(uint32_t base, int row, int col, int l) {
    return base + (uint32_t)((row + (l & 15)) * GROW + (col + (l >> 4) * 8) * 2);
}
__device__ __forceinline__ uint32_t addrB80(uint32_t base, int row, int col, int l) {
    return base + (uint32_t)((row + ((l >> 4) & 1) * 8 + (l & 7)) * GROW
                             + (col + ((l >> 3) & 1) * 8) * 2);
}

// ---------------------------------------------------------------------------
// conversions
// ---------------------------------------------------------------------------
__global__ void split_two(const float* __restrict__ x0, const float* __restrict__ x1,
                          __half* __restrict__ h0, __half* __restrict__ l0p,
                          __half* __restrict__ h1, __half* __restrict__ l1p, int n4)
{
    int i = blockIdx.x * blockDim.x + threadIdx.x;
    const float* x = (i < n4) ? x0 : x1;
    __half* hh = (i < n4) ? h0 : h1;
    __half* ll = (i < n4) ? l0p : l1p;
    int j = (i < n4) ? i : i - n4;
    float4 v = ((const float4*)x)[j];
    uint32_t a, b, c, d;
    split2h(v.x, v.y, a, b);
    split2h(v.z, v.w, c, d);
    ((uint32_t*)hh)[j * 2]     = a;
    ((uint32_t*)hh)[j * 2 + 1] = c;
    ((uint32_t*)ll)[j * 2]     = b;
    ((uint32_t*)ll)[j * 2 + 1] = d;
}

__global__ void cvtT_W(const float* __restrict__ Wq, const float* __restrict__ Wkv,
                       const float* __restrict__ Wo,
                       __half* __restrict__ wqThi, __half* __restrict__ wqTlo,
                       __half* __restrict__ wkvThi, __half* __restrict__ wkvTlo,
                       __half* __restrict__ woT)
{
    __shared__ float tile[32][33];
    int bx = blockIdx.x;
    const float* W; __half *Thi, *Tlo; int Nc, idx, do_split;
    if (bx < 256)      { W = Wq;  Thi = wqThi;  Tlo = wqTlo;  Nc = 512;  idx = bx;       do_split = 1; }
    else if (bx < 768) { W = Wkv; Thi = wkvThi; Tlo = wkvTlo; Nc = 1024; idx = bx - 256; do_split = 1; }
    else               { W = Wo;  Thi = woT;    Tlo = 0;      Nc = 512;  idx = bx - 768; do_split = 0; }
    int tn = Nc / 32;
    int n0 = (idx % tn) * 32, k0 = (idx / tn) * 32;
    for (int r = threadIdx.y; r < 32; r += 8)
        tile[r][threadIdx.x] = W[(size_t)(k0 + r) * Nc + n0 + threadIdx.x];
    __syncthreads();
    for (int r = threadIdx.y; r < 32; r += 8) {
        float x = tile[threadIdx.x][r];
        __half h = __float2half_rn(x);
        size_t o = (size_t)(n0 + r) * 512 + k0 + threadIdx.x;
        Thi[o] = h;
        if (do_split) Tlo[o] = __float2half_rn(x - __half2float(h));
    }
}

// ---------------------------------------------------------------------------
// GEMM tile: out[128x128] = (Ahi+Alo)[128x512] @ WT^T, 2/3 fp16 terms.
// BK=32, 2-stage cp.async pipeline, ONE barrier per chunk.
// 8 warps (2m x 4n), warp tile 64x32.
// mode 0: fp32 out; mode 1: fp16 2-split out; mode 2: fp16 single out.
// ---------------------------------------------------------------------------
__device__ __forceinline__ void gemm_body(
    const __half* __restrict__ Ahi, const __half* __restrict__ Alo,
    const __half* __restrict__ WThi, const __half* __restrict__ WTlo,
    int m0, int n0w, int n0out, int terms, int mode,
    float* __restrict__ outf, __half* __restrict__ outhi, __half* __restrict__ outlo,
    char* smem)
{
    const uint32_t sb = smem_u32(smem);
    const int t = threadIdx.x, l = t & 31, w = t >> 5;
    const int wm = w >> 2, wn = w & 3;

    float c[4][4][4];
    #pragma unroll
    for (int i = 0; i < 4; i++)
        #pragma unroll
        for (int j = 0; j < 4; j++)
            #pragma unroll
            for (int e = 0; e < 4; e++) c[i][j][e] = 0.f;

    const int row = t >> 1, half = t & 1;
    // per-thread global sources (chunk 0), advance by 32 halves per chunk
    const __half* gAh = Ahi  + (size_t)(m0 + row) * 512 + half * 16;
    const __half* gAl = Alo  + (size_t)(m0 + row) * 512 + half * 16;
    const __half* gWh = WThi + (size_t)(n0w + row) * 512 + half * 16;
    const __half* gWl = (terms == 3) ? WTlo + (size_t)(n0w + row) * 512 + half * 16 : gWh;
    const uint32_t db = (uint32_t)(row * GROW + half * 32);

    // issue chunk c into stage st
    auto issue = [&](int c2, int st) {
        uint32_t so = sb + (uint32_t)st * GSTG + db;
        int ko = c2 * 32;
        cpa16(so + 0 * GBUF,      gAh + ko);
        cpa16(so + 0 * GBUF + 16, gAh + ko + 8);
        cpa16(so + 1 * GBUF,      gAl + ko);
        cpa16(so + 1 * GBUF + 16, gAl + ko + 8);
        cpa16(so + 2 * GBUF,      gWh + ko);
        cpa16(so + 2 * GBUF + 16, gWh + ko + 8);
        if (terms == 3) {
            cpa16(so + 3 * GBUF,      gWl + ko);
            cpa16(so + 3 * GBUF + 16, gWl + ko + 8);
        }
        CP_COMMIT();
    };

    issue(0, 0);

    for (int c2 = 0; c2 < 16; c2++) {
        CP_WAIT0();          // chunk c2 arrived
        __syncthreads();     // everyone done with prior stage + sees chunk c2
        if (c2 < 15) issue(c2 + 1, (c2 + 1) & 1);

        const uint32_t st = sb + (uint32_t)(c2 & 1) * GSTG;
        const uint32_t sAh = st, sAl = st + GBUF, sWh = st + 2 * GBUF, sWl = st + 3 * GBUF;

        #pragma unroll
        for (int kk = 0; kk < 2; kk++) {
            uint32_t ah[4][4], al[4][4];
            #pragma unroll
            for (int i = 0; i < 4; i++) {
                ldsm4(ah[i], addrA80(sAh, wm * 64 + i * 16, kk * 16, l));
                ldsm4(al[i], addrA80(sAl, wm * 64 + i * 16, kk * 16, l));
            }
            #pragma unroll
            for (int p = 0; p < 2; p++) {
                uint32_t bh[4], bl[4];
                ldsm4(bh, addrB80(sWh, wn * 32 + p * 16, kk * 16, l));
                if (terms == 3) ldsm4(bl, addrB80(sWl, wn * 32 + p * 16, kk * 16, l));
                #pragma unroll
                for (int i = 0; i < 4; i++) {
                    #pragma unroll
                    for (int q = 0; q < 2; q++) {
                        float* acc = c[i][p * 2 + q];
                        mma16816(acc, ah[i], bh + q * 2);
                        mma16816(acc, al[i], bh + q * 2);
                        if (terms == 3) mma16816(acc, ah[i], bl + q * 2);
                    }
                }
            }
        }
    }

    #pragma unroll
    for (int i = 0; i < 4; i++) {
        #pragma unroll
        for (int jn = 0; jn < 4; jn++) {
            int r0 = m0 + wm * 64 + i * 16 + (l >> 2);
            int cc = n0out + wn * 32 + jn * 8 + (l & 3) * 2;
            float* acc = c[i][jn];
            if (mode == 0) {
                *(float2*)(outf + (size_t)r0 * 512 + cc)       = make_float2(acc[0], acc[1]);
                *(float2*)(outf + (size_t)(r0 + 8) * 512 + cc) = make_float2(acc[2], acc[3]);
            } else if (mode == 1) {
                uint32_t h0, l0, h1, l1;
                split2h(acc[0], acc[1], h0, l0);
                split2h(acc[2], acc[3], h1, l1);
                *(uint32_t*)(outhi + (size_t)r0 * 512 + cc)       = h0;
                *(uint32_t*)(outlo + (size_t)r0 * 512 + cc)       = l0;
                *(uint32_t*)(outhi + (size_t)(r0 + 8) * 512 + cc) = h1;
                *(uint32_t*)(outlo + (size_t)(r0 + 8) * 512 + cc) = l1;
            } else {
                *(uint32_t*)(outhi + (size_t)r0 * 512 + cc)       = pack2h(acc[0], acc[1]);
                *(uint32_t*)(outhi + (size_t)(r0 + 8) * 512 + cc) = pack2h(acc[2], acc[3]);
            }
        }
    }
}

// grid (12, 64): bx 0-3 Q (3t, split out), 4-7 K (3t, split out), 8-11 V (2t)
__global__ __launch_bounds__(256, 2)
void proj_qkv(const __half* __restrict__ curhi, const __half* __restrict__ curlo,
              const __half* __restrict__ hidhi, const __half* __restrict__ hidlo,
              const __half* __restrict__ wqThi, const __half* __restrict__ wqTlo,
              const __half* __restrict__ wkvThi, const __half* __restrict__ wkvTlo,
              __half* __restrict__ qhi, __half* __restrict__ qlo,
              __half* __restrict__ khi, __half* __restrict__ klo,
              __half* __restrict__ vv)
{
    extern __shared__ __align__(1024) char smem[];
    int bx = blockIdx.x, m0 = blockIdx.y * 128;
    if (bx < 4)
        gemm_body(curhi, curlo, wqThi, wqTlo, m0, bx * 128, bx * 128, 3, 1,
                  nullptr, qhi, qlo, smem);
    else if (bx < 8)
        gemm_body(hidhi, hidlo, wkvThi, wkvTlo, m0, (bx - 4) * 128, (bx - 4) * 128,
                  3, 1, nullptr, khi, klo, smem);
    else
        gemm_body(hidhi, hidlo, wkvThi, wkvTlo, m0, 512 + (bx - 8) * 128,
                  (bx - 8) * 128, 2, 2, nullptr, vv, nullptr, smem);
}

__global__ __launch_bounds__(256, 2)
void proj_out(const __half* __restrict__ aohi, const __half* __restrict__ aolo,
              const __half* __restrict__ woT, float* __restrict__ out)
{
    extern __shared__ __align__(1024) char smem[];
    gemm_body(aohi, aolo, woT, nullptr, blockIdx.y * 128, blockIdx.x * 128,
              blockIdx.x * 128, 2, 0, out, nullptr, nullptr, smem);
}

// ---------------------------------------------------------------------------
// Attention, online-max softmax w/ lazy rescale (NO 1/sqrt(d) scale).
// Block = (b,h) x 128 q-rows, 8 warps x 16 q-rows, two CTAs per SM.
// 2-stage KV pipeline, ONE barrier per k-tile.
// S: Q 2-split x K 2-split (3 terms). P: single fp16. PV: 1 term.
// ---------------------------------------------------------------------------
__global__ __launch_bounds__(256, 2)
void attn_mma(const __half* __restrict__ Qhi, const __half* __restrict__ Qlo,
              const __half* __restrict__ Khi, const __half* __restrict__ Klo,
              const __half* __restrict__ Vv,
              __half* __restrict__ AOhi, __half* __restrict__ AOlo)
{
    extern __shared__ __align__(1024) char smem[];
    const uint32_t sb = smem_u32(smem);
    const uint32_t sQh = sb, sQl = sb + GB;
    const uint32_t kvbase = sb + 2 * GB;     // two stages of (Kh,Kl,V)

    const int t = threadIdx.x, l = t & 31, w = t >> 5;
    const int b = blockIdx.x >> 3, h = blockIdx.x & 7;
    const int q0 = blockIdx.y * 128;

    // stage resident Q tile (plain stores; covered by first __syncthreads)
    {
        const int row = t >> 1, half = t & 1;
        const __half* gh = Qhi + (size_t)(b * N_ + q0 + row) * 512 + h * 64 + half * 32;
        const __half* gl = Qlo + (size_t)(b * N_ + q0 + row) * 512 + h * 64 + half * 32;
        char* dh = smem +      row * 144 + half * 64;
        char* dl = smem + GB + row * 144 + half * 64;
        #pragma unroll
        for (int v = 0; v < 4; v++) {
            ((uint4*)dh)[v] = ((const uint4*)gh)[v];
            ((uint4*)dl)[v] = ((const uint4*)gl)[v];
        }
    }

    // KV staging: 384 half-row tasks over 256 threads
    auto issue_kv = [&](int kt, int st) {
        uint32_t stb = kvbase + (uint32_t)st * KVSTG;
        for (int i = t; i < 384; i += 256) {
            int buf = i >> 7, rr = (i & 127) >> 1, hf = i & 1;
            const __half* base = (buf == 0) ? Khi : (buf == 1) ? Klo : Vv;
            const __half* src = base + (size_t)(b * N_ + kt * 64 + rr) * 512
                                + h * 64 + hf * 32;
            uint32_t d = stb + (uint32_t)(buf * KVB + rr * 144 + hf * 64);
            #pragma unroll
            for (int v = 0; v < 4; v++)
                cpa16(d + v * 16, src + v * 8);
        }
        CP_COMMIT();
    };

    issue_kv(0, 0);

    float o[8][4];
    #pragma unroll
    for (int i = 0; i < 8; i++)
        #pragma unroll
        for (int e = 0; e < 4; e++) o[i][e] = 0.f;
    float lsum0 = 0.f, lsum1 = 0.f;
    float m0r = -1e30f, m1r = -1e30f;

    for (int kt = 0; kt < 16; kt++) {
        CP_WAIT0();          // tile kt arrived
        __syncthreads();     // all warps done with other stage + see tile kt
        if (kt < 15) issue_kv(kt + 1, (kt + 1) & 1);

        const uint32_t stb = kvbase + (uint32_t)(kt & 1) * KVSTG;
        const uint32_t sKh = stb, sKl = stb + KVB, sV = stb + 2 * KVB;

        // ---- S = Q K^T (3 terms) ----
        float s[8][4];
        #pragma unroll
        for (int i = 0; i < 8; i++)
            #pragma unroll
            for (int e = 0; e < 4; e++) s[i][e] = 0.f;

        #pragma unroll
        for (int kk = 0; kk < 4; kk++) {
            uint32_t qh[4], ql[4];
            ldsm4(qh, addrA(sQh, w * 16, kk * 16, l));
            ldsm4(ql, addrA(sQl, w * 16, kk * 16, l));
            #pragma unroll
            for (int p = 0; p < 4; p++) {
                uint32_t bh[4], bl[4];
                ldsm4(bh, addrB(sKh, p * 16, kk * 16, l));
                ldsm4(bl, addrB(sKl, p * 16, kk * 16, l));
                #pragma unroll
                for (int q = 0; q < 2; q++) {
                    float* acc = s[p * 2 + q];
                    mma16816(acc, qh, bh + q * 2);
                    mma16816(acc, ql, bh + q * 2);
                    mma16816(acc, qh, bl + q * 2);
                }
            }
        }

        // ---- online max; rescale only if max advanced (warp-uniform) ----
        float rm0 = -1e30f, rm1 = -1e30f;
        #pragma unroll
        for (int jn = 0; jn < 8; jn++) {
            rm0 = fmaxf(rm0, fmaxf(s[jn][0], s[jn][1]));
            rm1 = fmaxf(rm1, fmaxf(s[jn][2], s[jn][3]));
        }
        rm0 = fmaxf(rm0, __shfl_xor_sync(0xffffffffu, rm0, 1));
        rm0 = fmaxf(rm0, __shfl_xor_sync(0xffffffffu, rm0, 2));
        rm1 = fmaxf(rm1, __shfl_xor_sync(0xffffffffu, rm1, 1));
        rm1 = fmaxf(rm1, __shfl_xor_sync(0xffffffffu, rm1, 2));
        if (rm0 > m0r) {
            float sc0 = __expf(m0r - rm0);
            m0r = rm0;
            lsum0 *= sc0;
            #pragma unroll
            for (int i = 0; i < 8; i++) { o[i][0] *= sc0; o[i][1] *= sc0; }
        }
        if (rm1 > m1r) {
            float sc1 = __expf(m1r - rm1);
            m1r = rm1;
            lsum1 *= sc1;
            #pragma unroll
            for (int i = 0; i < 8; i++) { o[i][2] *= sc1; o[i][3] *= sc1; }
        }

        // ---- exp + row sums + pack P (single fp16; P in [0,1]) ----
        uint32_t pa[4][4];
        #pragma unroll
        for (int jn = 0; jn < 8; jn++) {
            float e0 = __expf(s[jn][0] - m0r);
            float e1 = __expf(s[jn][1] - m0r);
            float e2 = __expf(s[jn][2] - m1r);
            float e3 = __expf(s[jn][3] - m1r);
            lsum0 += e0 + e1;
            lsum1 += e2 + e3;
            int kj = jn >> 1, base = (jn & 1) * 2;
            pa[kj][base + 0] = pack2h(e0, e1);
            pa[kj][base + 1] = pack2h(e2, e3);
        }

        // ---- O += P V (1 term) ----
        #pragma unroll
        for (int kj = 0; kj < 4; kj++) {
            #pragma unroll
            for (int pd = 0; pd < 4; pd++) {
                uint32_t bv[4];
                uint32_t va = (uint32_t)((kj * 16 + ((l >> 3) & 1) * 8 + (l & 7)) * 144
                                         + (pd * 16 + ((l >> 4) & 1) * 8) * 2);
                ldsm4t(bv, sV + va);
                #pragma unroll
                for (int q = 0; q < 2; q++)
                    mma16816(o[pd * 2 + q], pa[kj], bv + q * 2);
            }
        }
    }

    lsum0 += __shfl_xor_sync(0xffffffffu, lsum0, 1);
    lsum0 += __shfl_xor_sync(0xffffffffu, lsum0, 2);
    lsum1 += __shfl_xor_sync(0xffffffffu, lsum1, 1);
    lsum1 += __shfl_xor_sync(0xffffffffu, lsum1, 2);
    float inv0 = 1.f / lsum0, inv1 = 1.f / lsum1;

    const int rowg = b * N_ + q0 + w * 16 + (l >> 2);
    #pragma unroll
    for (int dn = 0; dn < 8; dn++) {
        int cc = h * 64 + dn * 8 + (l & 3) * 2;
        uint32_t h0, l0, h1, l1;
        split2h(o[dn][0] * inv0, o[dn][1] * inv0, h0, l0);
        split2h(o[dn][2] * inv1, o[dn][3] * inv1, h1, l1);
        *(uint32_t*)(AOhi + (size_t)rowg * 512 + cc)       = h0;
        *(uint32_t*)(AOlo + (size_t)rowg * 512 + cc)       = l0;
        *(uint32_t*)(AOhi + (size_t)(rowg + 8) * 512 + cc) = h1;
        *(uint32_t*)(AOlo + (size_t)(rowg + 8) * 512 + cc) = l1;
    }
}

// ---------------------------------------------------------------------------
extern "C" void kernel_launch(void* const* d_in, const int* in_sizes, int n_in,
                              void* d_out, int out_size)
{
    (void)in_sizes; (void)n_in; (void)out_size;
    const float* current = (const float*)d_in[0];
    const float* hidden  = (const float*)d_in[1];
    const float* Wq      = (const float*)d_in[2];
    const float* Wkv     = (const float*)d_in[3];
    const float* Wo      = (const float*)d_in[4];
    float* out           = (float*)d_out;

    __half *curhi, *curlo, *hidhi, *hidlo;
    __half *wqThi, *wqTlo, *wkvThi, *wkvTlo, *woT;
    __half *qhi, *qlo, *khi, *klo, *vv, *aohi, *aolo;
    cudaGetSymbolAddress((void**)&curhi, g_curhi); cudaGetSymbolAddress((void**)&curlo, g_curlo);
    cudaGetSymbolAddress((void**)&hidhi, g_hidhi); cudaGetSymbolAddress((void**)&hidlo, g_hidlo);
    cudaGetSymbolAddress((void**)&wqThi, g_wqThi); cudaGetSymbolAddress((void**)&wqTlo, g_wqTlo);
    cudaGetSymbolAddress((void**)&wkvThi, g_wkvThi); cudaGetSymbolAddress((void**)&wkvTlo, g_wkvTlo);
    cudaGetSymbolAddress((void**)&woT, g_woT);
    cudaGetSymbolAddress((void**)&qhi, g_qhi);   cudaGetSymbolAddress((void**)&qlo, g_qlo);
    cudaGetSymbolAddress((void**)&khi, g_khi);   cudaGetSymbolAddress((void**)&klo, g_klo);
    cudaGetSymbolAddress((void**)&vv,  g_v);
    cudaGetSymbolAddress((void**)&aohi, g_aohi); cudaGetSymbolAddress((void**)&aolo, g_aolo);

    const int gemm_smem = 2 * GSTG;                  // 81920
    const int attn_smem = 2 * GB + 2 * KVSTG;        // 92160
    cudaFuncSetAttribute(proj_qkv, cudaFuncAttributeMaxDynamicSharedMemorySize, gemm_smem);
    cudaFuncSetAttribute(proj_out, cudaFuncAttributeMaxDynamicSharedMemorySize, gemm_smem);
    cudaFuncSetAttribute(attn_mma, cudaFuncAttributeMaxDynamicSharedMemorySize, attn_smem);

    const int n4 = MT_ * DM_ / 4;
    split_two<<<2 * n4 / 256, 256>>>(current, hidden, curhi, curlo, hidhi, hidlo, n4);
    cvtT_W<<<1024, dim3(32, 8)>>>(Wq, Wkv, Wo, wqThi, wqTlo, wkvThi, wkvTlo, woT);

    proj_qkv<<<dim3(12, 64), 256, gemm_smem>>>(curhi, curlo, hidhi, hidlo,
                                               wqThi, wqTlo, wkvThi, wkvTlo,
                                               qhi, qlo, khi, klo, vv);
    attn_mma<<<dim3(B_ * H_, N_ / 128), 256, attn_smem>>>(qhi, qlo, khi, klo, vv,
                                                          aohi, aolo);
    proj_out<<<dim3(4, 64), 256, gemm_smem>>>(aohi, aolo, woT, out);
}

// round 12
// speedup vs baseline: 1.5707x; 1.0204x over previous
#include <cuda_runtime.h>
#include <cuda_fp16.h>
#include <cstdint>
#include <math.h>

#define B_   8
#define N_   1024
#define DM_  512
#define H_   8
#define MT_  (B_ * N_)      // 8192
#define GB   18432          // 128 rows x 144 B (Q tiles in attention)

// GEMM pipeline geometry: BK=32, rows of 80 B, 4 buffers, 2 stages
#define GROW 80
#define GBUF 10240          // 128 * 80
#define GSTG 40960          // 4 * GBUF
// Attention KV stage: 3 buffers x (64 rows x 144 B)
#define KVB  9216
#define KVSTG (3 * KVB)     // 27648

// ---------------- fp16 scratch (__device__ globals; no allocs) -------------
__device__ __half g_curhi[MT_ * DM_], g_curlo[MT_ * DM_];
__device__ __half g_hidhi[MT_ * DM_], g_hidlo[MT_ * DM_];
__device__ __half g_wqThi [DM_ * DM_],     g_wqTlo [DM_ * DM_];
__device__ __half g_wkvThi[2 * DM_ * DM_], g_wkvTlo[2 * DM_ * DM_];
__device__ __half g_woT   [DM_ * DM_];
__device__ __half g_qhi[MT_ * DM_], g_qlo[MT_ * DM_];
__device__ __half g_khi[MT_ * DM_], g_klo[MT_ * DM_];
__device__ __half g_v  [MT_ * DM_];
__device__ __half g_aohi[MT_ * DM_], g_aolo[MT_ * DM_];

// ---------------- helpers ---------------------------------------------------
__device__ __forceinline__ uint32_t smem_u32(const void* p) {
    uint32_t a;
    asm("{ .reg .u64 t; cvta.to.shared.u64 t, %1; cvt.u32.u64 %0, t; }" : "=r"(a) : "l"(p));
    return a;
}
__device__ __forceinline__ void cpa16(uint32_t dst, const void* src) {
    asm volatile("cp.async.cg.shared.global [%0], [%1], 16;" :: "r"(dst), "l"(src));
}
#define CP_COMMIT() asm volatile("cp.async.commit_group;" ::: "memory")
#define CP_WAIT0()  asm volatile("cp.async.wait_group 0;" ::: "memory")

__device__ __forceinline__ void ldsm4(uint32_t* r, uint32_t addr) {
    asm volatile("ldmatrix.sync.aligned.m8n8.x4.shared.b16 {%0,%1,%2,%3}, [%4];"
        : "=r"(r[0]), "=r"(r[1]), "=r"(r[2]), "=r"(r[3]) : "r"(addr));
}
__device__ __forceinline__ void ldsm4t(uint32_t* r, uint32_t addr) {
    asm volatile("ldmatrix.sync.aligned.m8n8.x4.trans.shared.b16 {%0,%1,%2,%3}, [%4];"
        : "=r"(r[0]), "=r"(r[1]), "=r"(r[2]), "=r"(r[3]) : "r"(addr));
}
__device__ __forceinline__ void mma16816(float* c, const uint32_t* a, const uint32_t* b) {
    asm volatile("mma.sync.aligned.m16n8k16.row.col.f32.f16.f16.f32 "
        "{%0,%1,%2,%3}, {%4,%5,%6,%7}, {%8,%9}, {%0,%1,%2,%3};"
        : "+f"(c[0]), "+f"(c[1]), "+f"(c[2]), "+f"(c[3])
        : "r"(a[0]), "r"(a[1]), "r"(a[2]), "r"(a[3]), "r"(b[0]), "r"(b[1]));
}
__device__ __forceinline__ uint32_t hpack(__half a, __half b) {
    __half2 t; t.x = a; t.y = b;
    return *(uint32_t*)&t;
}
__device__ __forceinline__ uint32_t pack2h(float v0, float v1) {
    return hpack(__float2half_rn(v0), __float2half_rn(v1));
}
__device__ __forceinline__ void split2h(float v0, float v1, uint32_t& hi, uint32_t& lo) {
    __half h0 = __float2half_rn(v0), h1 = __float2half_rn(v1);
    __half l0 = __float2half_rn(v0 - __half2float(h0));
    __half l1 = __float2half_rn(v1 - __half2float(h1));
    hi = hpack(h0, h1); lo = hpack(l0, l1);
}
// packed {lo = t0, hi = t1} fp16x2 from two fp32
__device__ __forceinline__ uint32_t cvt_f16x2(float t0, float t1) {
    uint32_t r;
    asm("cvt.rn.f16x2.f32 %0, %1, %2;" : "=r"(r) : "f"(t1), "f"(t0));
    return r;
}
__device__ __forceinline__ uint32_t ex2_f16x2(uint32_t x) {
    uint32_t r;
    asm("ex2.approx.f16x2 %0, %1;" : "=r"(r) : "r"(x));
    return r;
}

// 144-B-stride tiles (attention Q / KV) -> conflict-free ldmatrix
__device__ __forceinline__ uint32_t addrA(uint32_t base, int row, int col, int l) {
    return base + (uint32_t)((row + (l & 15)) * 144 + (col + (l >> 4) * 8) * 2);
}
__device__ __forceinline__ uint32_t addrB(uint32_t base, int row, int col, int l) {
    return base + (uint32_t)((row + ((l >> 4) & 1) * 8 + (l & 7)) * 144
                             + (col + ((l >> 3) & 1) * 8) * 2);
}
// 80-B-stride tiles (GEMM, BK=32)
__device__ __forceinline__ uint32_t addrA80(uint32_t base, int row, int col, int l) {
    return base + (uint32_t)((row + (l & 15)) * GROW + (col + (l >> 4) * 8) * 2);
}
__device__ __forceinline__ uint32_t addrB80(uint32_t base, int row, int col, int l) {
    return base + (uint32_t)((row + ((l >> 4) & 1) * 8 + (l & 7)) * GROW
                             + (col + ((l >> 3) & 1) * 8) * 2);
}

// ---------------------------------------------------------------------------
// conversions
// ---------------------------------------------------------------------------
__global__ void split_two(const float* __restrict__ x0, const float* __restrict__ x1,
                          __half* __restrict__ h0, __half* __restrict__ l0p,
                          __half* __restrict__ h1, __half* __restrict__ l1p, int n4)
{
    int i = blockIdx.x * blockDim.x + threadIdx.x;
    const float* x = (i < n4) ? x0 : x1;
    __half* hh = (i < n4) ? h0 : h1;
    __half* ll = (i < n4) ? l0p : l1p;
    int j = (i < n4) ? i : i - n4;
    float4 v = ((const float4*)x)[j];
    uint32_t a, b, c, d;
    split2h(v.x, v.y, a, b);
    split2h(v.z, v.w, c, d);
    ((uint32_t*)hh)[j * 2]     = a;
    ((uint32_t*)hh)[j * 2 + 1] = c;
    ((uint32_t*)ll)[j * 2]     = b;
    ((uint32_t*)ll)[j * 2 + 1] = d;
}

__global__ void cvtT_W(const float* __restrict__ Wq, const float* __restrict__ Wkv,
                       const float* __restrict__ Wo,
                       __half* __restrict__ wqThi, __half* __restrict__ wqTlo,
                       __half* __restrict__ wkvThi, __half* __restrict__ wkvTlo,
                       __half* __restrict__ woT)
{
    __shared__ float tile[32][33];
    int bx = blockIdx.x;
    const float* W; __half *Thi, *Tlo; int Nc, idx, do_split;
    if (bx < 256)      { W = Wq;  Thi = wqThi;  Tlo = wqTlo;  Nc = 512;  idx = bx;       do_split = 1; }
    else if (bx < 768) { W = Wkv; Thi = wkvThi; Tlo = wkvTlo; Nc = 1024; idx = bx - 256; do_split = 1; }
    else               { W = Wo;  Thi = woT;    Tlo = 0;      Nc = 512;  idx = bx - 768; do_split = 0; }
    int tn = Nc / 32;
    int n0 = (idx % tn) * 32, k0 = (idx / tn) * 32;
    for (int r = threadIdx.y; r < 32; r += 8)
        tile[r][threadIdx.x] = W[(size_t)(k0 + r) * Nc + n0 + threadIdx.x];
    __syncthreads();
    for (int r = threadIdx.y; r < 32; r += 8) {
        float x = tile[threadIdx.x][r];
        __half h = __float2half_rn(x);
        size_t o = (size_t)(n0 + r) * 512 + k0 + threadIdx.x;
        Thi[o] = h;
        if (do_split) Tlo[o] = __float2half_rn(x - __half2float(h));
    }
}

// ---------------------------------------------------------------------------
// GEMM tile: out[128x128] = (Ahi+Alo)[128x512] @ WT^T, 2/3 fp16 terms.
// BK=32, 2-stage cp.async pipeline, ONE barrier per chunk. 8 warps (2m x 4n).
// ---------------------------------------------------------------------------
__device__ __forceinline__ void gemm_body(
    const __half* __restrict__ Ahi, const __half* __restrict__ Alo,
    const __half* __restrict__ WThi, const __half* __restrict__ WTlo,
    int m0, int n0w, int n0out, int terms, int mode,
    float* __restrict__ outf, __half* __restrict__ outhi, __half* __restrict__ outlo,
    char* smem)
{
    const uint32_t sb = smem_u32(smem);
    const int t = threadIdx.x, l = t & 31, w = t >> 5;
    const int wm = w >> 2, wn = w & 3;

    float c[4][4][4];
    #pragma unroll
    for (int i = 0; i < 4; i++)
        #pragma unroll
        for (int j = 0; j < 4; j++)
            #pragma unroll
            for (int e = 0; e < 4; e++) c[i][j][e] = 0.f;

    const int row = t >> 1, half = t & 1;
    const __half* gAh = Ahi  + (size_t)(m0 + row) * 512 + half * 16;
    const __half* gAl = Alo  + (size_t)(m0 + row) * 512 + half * 16;
    const __half* gWh = WThi + (size_t)(n0w + row) * 512 + half * 16;
    const __half* gWl = (terms == 3) ? WTlo + (size_t)(n0w + row) * 512 + half * 16 : gWh;
    const uint32_t db = (uint32_t)(row * GROW + half * 32);

    auto issue = [&](int c2, int st) {
        uint32_t so = sb + (uint32_t)st * GSTG + db;
        int ko = c2 * 32;
        cpa16(so + 0 * GBUF,      gAh + ko);
        cpa16(so + 0 * GBUF + 16, gAh + ko + 8);
        cpa16(so + 1 * GBUF,      gAl + ko);
        cpa16(so + 1 * GBUF + 16, gAl + ko + 8);
        cpa16(so + 2 * GBUF,      gWh + ko);
        cpa16(so + 2 * GBUF + 16, gWh + ko + 8);
        if (terms == 3) {
            cpa16(so + 3 * GBUF,      gWl + ko);
            cpa16(so + 3 * GBUF + 16, gWl + ko + 8);
        }
        CP_COMMIT();
    };

    issue(0, 0);

    for (int c2 = 0; c2 < 16; c2++) {
        CP_WAIT0();
        __syncthreads();
        if (c2 < 15) issue(c2 + 1, (c2 + 1) & 1);

        const uint32_t st = sb + (uint32_t)(c2 & 1) * GSTG;
        const uint32_t sAh = st, sAl = st + GBUF, sWh = st + 2 * GBUF, sWl = st + 3 * GBUF;

        #pragma unroll
        for (int kk = 0; kk < 2; kk++) {
            uint32_t ah[4][4], al[4][4];
            #pragma unroll
            for (int i = 0; i < 4; i++) {
                ldsm4(ah[i], addrA80(sAh, wm * 64 + i * 16, kk * 16, l));
                ldsm4(al[i], addrA80(sAl, wm * 64 + i * 16, kk * 16, l));
            }
            #pragma unroll
            for (int p = 0; p < 2; p++) {
                uint32_t bh[4], bl[4];
                ldsm4(bh, addrB80(sWh, wn * 32 + p * 16, kk * 16, l));
                if (terms == 3) ldsm4(bl, addrB80(sWl, wn * 32 + p * 16, kk * 16, l));
                #pragma unroll
                for (int i = 0; i < 4; i++) {
                    #pragma unroll
                    for (int q = 0; q < 2; q++) {
                        float* acc = c[i][p * 2 + q];
                        mma16816(acc, ah[i], bh + q * 2);
                        mma16816(acc, al[i], bh + q * 2);
                        if (terms == 3) mma16816(acc, ah[i], bl + q * 2);
                    }
                }
            }
        }
    }

    #pragma unroll
    for (int i = 0; i < 4; i++) {
        #pragma unroll
        for (int jn = 0; jn < 4; jn++) {
            int r0 = m0 + wm * 64 + i * 16 + (l >> 2);
            int cc = n0out + wn * 32 + jn * 8 + (l & 3) * 2;
            float* acc = c[i][jn];
            if (mode == 0) {
                *(float2*)(outf + (size_t)r0 * 512 + cc)       = make_float2(acc[0], acc[1]);
                *(float2*)(outf + (size_t)(r0 + 8) * 512 + cc) = make_float2(acc[2], acc[3]);
            } else if (mode == 1) {
                uint32_t h0, l0, h1, l1;
                split2h(acc[0], acc[1], h0, l0);
                split2h(acc[2], acc[3], h1, l1);
                *(uint32_t*)(outhi + (size_t)r0 * 512 + cc)       = h0;
                *(uint32_t*)(outlo + (size_t)r0 * 512 + cc)       = l0;
                *(uint32_t*)(outhi + (size_t)(r0 + 8) * 512 + cc) = h1;
                *(uint32_t*)(outlo + (size_t)(r0 + 8) * 512 + cc) = l1;
            } else {
                *(uint32_t*)(outhi + (size_t)r0 * 512 + cc)       = pack2h(acc[0], acc[1]);
                *(uint32_t*)(outhi + (size_t)(r0 + 8) * 512 + cc) = pack2h(acc[2], acc[3]);
            }
        }
    }
}

__global__ __launch_bounds__(256, 2)
void proj_qkv(const __half* __restrict__ curhi, const __half* __restrict__ curlo,
              const __half* __restrict__ hidhi, const __half* __restrict__ hidlo,
              const __half* __restrict__ wqThi, const __half* __restrict__ wqTlo,
              const __half* __restrict__ wkvThi, const __half* __restrict__ wkvTlo,
              __half* __restrict__ qhi, __half* __restrict__ qlo,
              __half* __restrict__ khi, __half* __restrict__ klo,
              __half* __restrict__ vv)
{
    extern __shared__ __align__(1024) char smem[];
    int bx = blockIdx.x, m0 = blockIdx.y * 128;
    if (bx < 4)
        gemm_body(curhi, curlo, wqThi, wqTlo, m0, bx * 128, bx * 128, 3, 1,
                  nullptr, qhi, qlo, smem);
    else if (bx < 8)
        gemm_body(hidhi, hidlo, wkvThi, wkvTlo, m0, (bx - 4) * 128, (bx - 4) * 128,
                  3, 1, nullptr, khi, klo, smem);
    else
        gemm_body(hidhi, hidlo, wkvThi, wkvTlo, m0, 512 + (bx - 8) * 128,
                  (bx - 8) * 128, 2, 2, nullptr, vv, nullptr, smem);
}

__global__ __launch_bounds__(256, 2)
void proj_out(const __half* __restrict__ aohi, const __half* __restrict__ aolo,
              const __half* __restrict__ woT, float* __restrict__ out)
{
    extern __shared__ __align__(1024) char smem[];
    gemm_body(aohi, aolo, woT, nullptr, blockIdx.y * 128, blockIdx.x * 128,
              blockIdx.x * 128, 2, 0, out, nullptr, nullptr, smem);
}

// ---------------------------------------------------------------------------
// Attention, online-max softmax w/ lazy rescale (NO 1/sqrt(d) scale).
// Block = (b,h) x 128 q-rows, 8 warps x 16 q-rows, two CTAs per SM.
// 2-stage KV pipeline, ONE barrier per k-tile.
// S: Q 2-split x K 2-split (3 terms). P: ex2.approx.f16x2 (packed fp16 exp).
// lsum: extra mma with ones-column B fragment (fp32 tensor accumulation of
// the SAME fp16 P used in PV -> common-mode normalization). PV: 1 term.
// ---------------------------------------------------------------------------
__global__ __launch_bounds__(256, 2)
void attn_mma(const __half* __restrict__ Qhi, const __half* __restrict__ Qlo,
              const __half* __restrict__ Khi, const __half* __restrict__ Klo,
              const __half* __restrict__ Vv,
              __half* __restrict__ AOhi, __half* __restrict__ AOlo)
{
    extern __shared__ __align__(1024) char smem[];
    const uint32_t sb = smem_u32(smem);
    const uint32_t sQh = sb, sQl = sb + GB;
    const uint32_t kvbase = sb + 2 * GB;

    const int t = threadIdx.x, l = t & 31, w = t >> 5;
    const int b = blockIdx.x >> 3, h = blockIdx.x & 7;
    const int q0 = blockIdx.y * 128;
    const float LOG2E = 1.4426950408889634f;

    // B fragment: ones in column 0 (col = l>>2), zeros elsewhere
    uint32_t bones[2];
    bones[0] = bones[1] = ((l >> 2) == 0) ? 0x3C003C00u : 0u;

    // stage resident Q tile
    {
        const int row = t >> 1, half = t & 1;
        const __half* gh = Qhi + (size_t)(b * N_ + q0 + row) * 512 + h * 64 + half * 32;
        const __half* gl = Qlo + (size_t)(b * N_ + q0 + row) * 512 + h * 64 + half * 32;
        char* dh = smem +      row * 144 + half * 64;
        char* dl = smem + GB + row * 144 + half * 64;
        #pragma unroll
        for (int v = 0; v < 4; v++) {
            ((uint4*)dh)[v] = ((const uint4*)gh)[v];
            ((uint4*)dl)[v] = ((const uint4*)gl)[v];
        }
    }

    auto issue_kv = [&](int kt, int st) {
        uint32_t stb = kvbase + (uint32_t)st * KVSTG;
        for (int i = t; i < 384; i += 256) {
            int buf = i >> 7, rr = (i & 127) >> 1, hf = i & 1;
            const __half* base = (buf == 0) ? Khi : (buf == 1) ? Klo : Vv;
            const __half* src = base + (size_t)(b * N_ + kt * 64 + rr) * 512
                                + h * 64 + hf * 32;
            uint32_t d = stb + (uint32_t)(buf * KVB + rr * 144 + hf * 64);
            #pragma unroll
            for (int v = 0; v < 4; v++)
                cpa16(d + v * 16, src + v * 8);
        }
        CP_COMMIT();
    };

    issue_kv(0, 0);

    float o[8][4];
    #pragma unroll
    for (int i = 0; i < 8; i++)
        #pragma unroll
        for (int e = 0; e < 4; e++) o[i][e] = 0.f;
    float lsA[4] = {0.f, 0.f, 0.f, 0.f};     // row-sum accumulator (tensor)
    float m0r = -1e30f, m1r = -1e30f;
    float m0s = 0.f, m1s = 0.f;              // m * log2e

    for (int kt = 0; kt < 16; kt++) {
        CP_WAIT0();
        __syncthreads();
        if (kt < 15) issue_kv(kt + 1, (kt + 1) & 1);

        const uint32_t stb = kvbase + (uint32_t)(kt & 1) * KVSTG;
        const uint32_t sKh = stb, sKl = stb + KVB, sV = stb + 2 * KVB;

        // ---- S = Q K^T (3 terms) ----
        float s[8][4];
        #pragma unroll
        for (int i = 0; i < 8; i++)
            #pragma unroll
            for (int e = 0; e < 4; e++) s[i][e] = 0.f;

        #pragma unroll
        for (int kk = 0; kk < 4; kk++) {
            uint32_t qh[4], ql[4];
            ldsm4(qh, addrA(sQh, w * 16, kk * 16, l));
            ldsm4(ql, addrA(sQl, w * 16, kk * 16, l));
            #pragma unroll
            for (int p = 0; p < 4; p++) {
                uint32_t bh[4], bl[4];
                ldsm4(bh, addrB(sKh, p * 16, kk * 16, l));
                ldsm4(bl, addrB(sKl, p * 16, kk * 16, l));
                #pragma unroll
                for (int q = 0; q < 2; q++) {
                    float* acc = s[p * 2 + q];
                    mma16816(acc, qh, bh + q * 2);
                    mma16816(acc, ql, bh + q * 2);
                    mma16816(acc, qh, bl + q * 2);
                }
            }
        }

        // ---- online max; rescale only if max advanced (warp-uniform) ----
        float rm0 = -1e30f, rm1 = -1e30f;
        #pragma unroll
        for (int jn = 0; jn < 8; jn++) {
            rm0 = fmaxf(rm0, fmaxf(s[jn][0], s[jn][1]));
            rm1 = fmaxf(rm1, fmaxf(s[jn][2], s[jn][3]));
        }
        rm0 = fmaxf(rm0, __shfl_xor_sync(0xffffffffu, rm0, 1));
        rm0 = fmaxf(rm0, __shfl_xor_sync(0xffffffffu, rm0, 2));
        rm1 = fmaxf(rm1, __shfl_xor_sync(0xffffffffu, rm1, 1));
        rm1 = fmaxf(rm1, __shfl_xor_sync(0xffffffffu, rm1, 2));
        if (rm0 > m0r) {
            float sc0 = __expf(m0r - rm0);
            m0r = rm0; m0s = rm0 * LOG2E;
            lsA[0] *= sc0; lsA[1] *= sc0;
            #pragma unroll
            for (int i = 0; i < 8; i++) { o[i][0] *= sc0; o[i][1] *= sc0; }
        }
        if (rm1 > m1r) {
            float sc1 = __expf(m1r - rm1);
            m1r = rm1; m1s = rm1 * LOG2E;
            lsA[2] *= sc1; lsA[3] *= sc1;
            #pragma unroll
            for (int i = 0; i < 8; i++) { o[i][2] *= sc1; o[i][3] *= sc1; }
        }

        // ---- P = exp2((s - m) * log2e) via ex2.approx.f16x2 ----
        uint32_t pa[4][4];
        #pragma unroll
        for (int jn = 0; jn < 8; jn++) {
            float t0 = fmaf(s[jn][0], LOG2E, -m0s);
            float t1 = fmaf(s[jn][1], LOG2E, -m0s);
            float t2 = fmaf(s[jn][2], LOG2E, -m1s);
            float t3 = fmaf(s[jn][3], LOG2E, -m1s);
            int kj = jn >> 1, base = (jn & 1) * 2;
            pa[kj][base + 0] = ex2_f16x2(cvt_f16x2(t0, t1));
            pa[kj][base + 1] = ex2_f16x2(cvt_f16x2(t2, t3));
        }

        // ---- lsum += row-sums of P (tensor core, ones column) ----
        #pragma unroll
        for (int kj = 0; kj < 4; kj++)
            mma16816(lsA, pa[kj], bones);

        // ---- O += P V (1 term) ----
        #pragma unroll
        for (int kj = 0; kj < 4; kj++) {
            #pragma unroll
            for (int pd = 0; pd < 4; pd++) {
                uint32_t bv[4];
                uint32_t va = (uint32_t)((kj * 16 + ((l >> 3) & 1) * 8 + (l & 7)) * 144
                                         + (pd * 16 + ((l >> 4) & 1) * 8) * 2);
                ldsm4t(bv, sV + va);
                #pragma unroll
                for (int q = 0; q < 2; q++)
                    mma16816(o[pd * 2 + q], pa[kj], bv + q * 2);
            }
        }
    }

    // lsum for row (l>>2) sits in lane (l & 28), element 0 (col 0); row +8 in elem 2
    float ls0 = __shfl_sync(0xffffffffu, lsA[0], l & 28);
    float ls1 = __shfl_sync(0xffffffffu, lsA[2], l & 28);
    float inv0 = 1.f / ls0, inv1 = 1.f / ls1;

    const int rowg = b * N_ + q0 + w * 16 + (l >> 2);
    #pragma unroll
    for (int dn = 0; dn < 8; dn++) {
        int cc = h * 64 + dn * 8 + (l & 3) * 2;
        uint32_t h0, l0, h1, l1;
        split2h(o[dn][0] * inv0, o[dn][1] * inv0, h0, l0);
        split2h(o[dn][2] * inv1, o[dn][3] * inv1, h1, l1);
        *(uint32_t*)(AOhi + (size_t)rowg * 512 + cc)       = h0;
        *(uint32_t*)(AOlo + (size_t)rowg * 512 + cc)       = l0;
        *(uint32_t*)(AOhi + (size_t)(rowg + 8) * 512 + cc) = h1;
        *(uint32_t*)(AOlo + (size_t)(rowg + 8) * 512 + cc) = l1;
    }
}

// ---------------------------------------------------------------------------
extern "C" void kernel_launch(void* const* d_in, const int* in_sizes, int n_in,
                              void* d_out, int out_size)
{
    (void)in_sizes; (void)n_in; (void)out_size;
    const float* current = (const float*)d_in[0];
    const float* hidden  = (const float*)d_in[1];
    const float* Wq      = (const float*)d_in[2];
    const float* Wkv     = (const float*)d_in[3];
    const float* Wo      = (const float*)d_in[4];
    float* out           = (float*)d_out;

    __half *curhi, *curlo, *hidhi, *hidlo;
    __half *wqThi, *wqTlo, *wkvThi, *wkvTlo, *woT;
    __half *qhi, *qlo, *khi, *klo, *vv, *aohi, *aolo;
    cudaGetSymbolAddress((void**)&curhi, g_curhi); cudaGetSymbolAddress((void**)&curlo, g_curlo);
    cudaGetSymbolAddress((void**)&hidhi, g_hidhi); cudaGetSymbolAddress((void**)&hidlo, g_hidlo);
    cudaGetSymbolAddress((void**)&wqThi, g_wqThi); cudaGetSymbolAddress((void**)&wqTlo, g_wqTlo);
    cudaGetSymbolAddress((void**)&wkvThi, g_wkvThi); cudaGetSymbolAddress((void**)&wkvTlo, g_wkvTlo);
    cudaGetSymbolAddress((void**)&woT, g_woT);
    cudaGetSymbolAddress((void**)&qhi, g_qhi);   cudaGetSymbolAddress((void**)&qlo, g_qlo);
    cudaGetSymbolAddress((void**)&khi, g_khi);   cudaGetSymbolAddress((void**)&klo, g_klo);
    cudaGetSymbolAddress((void**)&vv,  g_v);
    cudaGetSymbolAddress((void**)&aohi, g_aohi); cudaGetSymbolAddress((void**)&aolo, g_aolo);

    const int gemm_smem = 2 * GSTG;                  // 81920
    const int attn_smem = 2 * GB + 2 * KVSTG;        // 92160
    cudaFuncSetAttribute(proj_qkv, cudaFuncAttributeMaxDynamicSharedMemorySize, gemm_smem);
    cudaFuncSetAttribute(proj_out, cudaFuncAttributeMaxDynamicSharedMemorySize, gemm_smem);
    cudaFuncSetAttribute(attn_mma, cudaFuncAttributeMaxDynamicSharedMemorySize, attn_smem);

    const int n4 = MT_ * DM_ / 4;
    split_two<<<2 * n4 / 256, 256>>>(current, hidden, curhi, curlo, hidhi, hidlo, n4);
    cvtT_W<<<1024, dim3(32, 8)>>>(Wq, Wkv, Wo, wqThi, wqTlo, wkvThi, wkvTlo, woT);

    proj_qkv<<<dim3(12, 64), 256, gemm_smem>>>(curhi, curlo, hidhi, hidlo,
                                               wqThi, wqTlo, wkvThi, wkvTlo,
                                               qhi, qlo, khi, klo, vv);
    attn_mma<<<dim3(B_ * H_, N_ / 128), 256, attn_smem>>>(qhi, qlo, khi, klo, vv,
                                                          aohi, aolo);
    proj_out<<<dim3(4, 64), 256, gemm_smem>>>(aohi, aolo, woT, out);
}